// round 12
// baseline (speedup 1.0000x reference)
#include <cuda_runtime.h>
#include <cuda_fp16.h>
#include <math.h>
#include <stdint.h>

// Fixed problem shape: B=8, H=W=64 -> T=4096, C=512
#define BB   8
#define TT   4096
#define CC   512
#define BTC  (BB*TT*CC)
#define GM   32768
#define GK   512

// ---------------- scratch ----------------
__device__ __half g_kh[BTC];          // k (fp16)
__device__ float  g_v [BTC];          // v -> y1 in place (fp32)
__device__ __half g_srh[BTC];         // sr (fp16)
__device__ __half g_a [BTC];          // GEMM A (xi, then sr*y2), fp16
__device__ __half g_w [4*CC*CC];      // weights, fp16

// ---------------- asm helpers ----------------
__device__ __forceinline__ uint32_t smem_u32(const void* p) {
    uint32_t a;
    asm("{ .reg .u64 t; cvta.to.shared.u64 t, %1; cvt.u32.u64 %0, t; }" : "=r"(a) : "l"(p));
    return a;
}
__device__ __forceinline__ void cp16(uint32_t d, const void* s) {
    asm volatile("cp.async.cg.shared.global [%0], [%1], 16;" :: "r"(d), "l"(s));
}
#define CP_COMMIT() asm volatile("cp.async.commit_group;" ::: "memory")
#define CP_WAIT0()  asm volatile("cp.async.wait_group 0;" ::: "memory")
#define CP_WAIT1()  asm volatile("cp.async.wait_group 1;" ::: "memory")

__device__ __forceinline__ void ldsm4(uint32_t* r, uint32_t a) {
    asm volatile("ldmatrix.sync.aligned.m8n8.x4.shared.b16 {%0,%1,%2,%3}, [%4];"
        : "=r"(r[0]), "=r"(r[1]), "=r"(r[2]), "=r"(r[3]) : "r"(a));
}
__device__ __forceinline__ void mma16816(float* c, const uint32_t* a, const uint32_t* b) {
    asm volatile("mma.sync.aligned.m16n8k16.row.col.f32.f16.f16.f32 "
        "{%0,%1,%2,%3}, {%4,%5,%6,%7}, {%8,%9}, {%0,%1,%2,%3};"
        : "+f"(c[0]), "+f"(c[1]), "+f"(c[2]), "+f"(c[3])
        : "r"(a[0]), "r"(a[1]), "r"(a[2]), "r"(a[3]), "r"(b[0]), "r"(b[1]));
}
#define SW64(o) ((o) ^ (((o) >> 3) & 0x30))

// one WKV recurrence step (state update only)
__device__ __forceinline__ void wkv_step(float kt, float vt, float w,
                                         float& p, float& q, float& o) {
    float wo = w + o;
    float d  = wo - kt;
    float e  = __expf(-fabsf(d));
    bool ge  = (d >= 0.f);
    float A  = ge ? 1.f : e;
    float Bv = ge ? e : 1.f;
    p = fmaf(A, p, Bv * vt);
    q = fmaf(A, q, Bv);
    o = fmaxf(wo, kt);
}
// output + state update
__device__ __forceinline__ float wkv_out_step(float kt, float vt, float w, float u,
                                              float& p, float& q, float& o) {
    float uk = u + kt;
    float d1 = o - uk;
    float e1 = __expf(-fabsf(d1));
    bool g1  = (d1 >= 0.f);
    float A1 = g1 ? 1.f : e1;
    float B1 = g1 ? e1 : 1.f;
    float y  = fmaf(A1, p, B1 * vt) / fmaf(A1, q, B1);
    wkv_step(kt, vt, w, p, q, o);
    return y;
}

// ---------------- kernel 1: q_shift + zigzag -> fp16 ----------------
__global__ void shift_zigzag_f16(const float* __restrict__ x, __half* __restrict__ a) {
    int gid = blockIdx.x * 256 + threadIdx.x;       // float4 units
    int c4 = gid & 127;
    int tp = (gid >> 7) & (TT - 1);
    int b  = gid >> 19;
    int i  = tp >> 6;
    int jj = tp & 63;
    int col = (i & 1) ? (63 - jj) : jj;
    int grp = c4 >> 5;
    int hs = i, ws = col;
    bool valid;
    if (grp == 0)      { ws = col - 1; valid = (col >= 1);  }
    else if (grp == 1) { ws = col + 1; valid = (col <= 62); }
    else if (grp == 2) { hs = i - 1;   valid = (i >= 1);    }
    else               { hs = i + 1;   valid = (i <= 62);   }
    float4 v = make_float4(0.f, 0.f, 0.f, 0.f);
    if (valid)
        v = *(const float4*)(x + ((size_t)((b << 12) + (hs << 6) + ws) << 9) + (c4 << 2));
    __half h[4] = {__float2half_rn(v.x), __float2half_rn(v.y),
                   __float2half_rn(v.z), __float2half_rn(v.w)};
    *(uint2*)(a + ((size_t)gid << 2)) = *(uint2*)h;
}

// ---------------- kernel 2: weight fp16 conversion ----------------
__global__ void conv_w4(const float* __restrict__ w0, const float* __restrict__ w1,
                        const float* __restrict__ w2, const float* __restrict__ w3,
                        __half* __restrict__ wo) {
    int gid = blockIdx.x * 256 + threadIdx.x;
    int sel = gid >> 18;
    int off = gid & (CC * CC - 1);
    const float* src = (sel == 0) ? w0 : (sel == 1) ? w1 : (sel == 2) ? w2 : w3;
    wo[gid] = __float2half_rn(src[off]);
}

// ---------------- GEMM: fp16 1-mma, 128x128 tiles, 3-stage pipe ------
#define TILE_B (128 * 64)
#define STG_B  (2 * TILE_B)        // 16 KB
#define SM_TOT (3 * STG_B)         // 48 KB

__device__ __forceinline__ void gemm_core(const __half* __restrict__ A,
                                          const __half* __restrict__ W,
                                          float* __restrict__ Co,
                                          __half* __restrict__ HCo,
                                          int m0, int n0, bool sigm, bool half_out,
                                          char* smem) {
    const int tid = threadIdx.x;
    const int wid = tid >> 5;
    const int lane = tid & 31;
    const int wm = (wid & 3) * 32;
    const int wn = (wid >> 2) * 64;
    const uint32_t sb0 = smem_u32(smem);

    float acc[2][8][4];
    #pragma unroll
    for (int i = 0; i < 2; i++)
        #pragma unroll
        for (int j = 0; j < 8; j++)
            #pragma unroll
            for (int q = 0; q < 4; q++) acc[i][j][q] = 0.f;

    auto load_stage = [&](int kc, int s) {
        uint32_t sb = sb0 + s * STG_B;
        #pragma unroll
        for (int i = 0; i < 2; i++) {
            int idx = tid + i * 256;
            int r = idx >> 2, c16 = idx & 3;
            uint32_t sw = SW64((uint32_t)(r * 64 + c16 * 16));
            size_t ga = (size_t)(m0 + r) * GK + kc * 32 + c16 * 8;
            size_t gb = (size_t)(n0 + r) * GK + kc * 32 + c16 * 8;
            cp16(sb + sw,          A + ga);
            cp16(sb + TILE_B + sw, W + gb);
        }
    };

    const int sub = lane >> 3, lrow = lane & 7;

    load_stage(0, 0); CP_COMMIT();
    load_stage(1, 1); CP_COMMIT();

    #pragma unroll 1
    for (int kc = 0; kc < 16; kc++) {
        if (kc < 14) { CP_WAIT1(); } else { CP_WAIT0(); }
        __syncthreads();
        if (kc + 2 < 16) {
            int s2 = (kc + 2) % 3;
            load_stage(kc + 2, s2); CP_COMMIT();
        }
        const uint32_t sb = sb0 + (kc % 3) * STG_B;

        #pragma unroll
        for (int k16 = 0; k16 < 2; k16++) {
            const uint32_t kbyte = (uint32_t)(k16 * 32 + (sub >> 1) * 16);
            uint32_t av[2][4], bh[8][2];
            #pragma unroll
            for (int mt = 0; mt < 2; mt++) {
                int row = wm + mt * 16 + (sub & 1) * 8 + lrow;
                uint32_t so = SW64((uint32_t)(row * 64) + kbyte);
                ldsm4(av[mt], sb + so);
            }
            #pragma unroll
            for (int nt = 0; nt < 4; nt++) {
                int row = wn + nt * 16 + (sub & 1) * 8 + lrow;
                uint32_t so = SW64((uint32_t)(row * 64) + kbyte);
                uint32_t t0[4];
                ldsm4(t0, sb + TILE_B + so);
                bh[2*nt][0] = t0[0]; bh[2*nt+1][0] = t0[1];
                bh[2*nt][1] = t0[2]; bh[2*nt+1][1] = t0[3];
            }
            #pragma unroll
            for (int mt = 0; mt < 2; mt++)
                #pragma unroll
                for (int n8 = 0; n8 < 8; n8++)
                    mma16816(acc[mt][n8], av[mt], bh[n8]);
        }
    }

    const int g = lane >> 2, t = lane & 3;
    #pragma unroll
    for (int mt = 0; mt < 2; mt++) {
        #pragma unroll
        for (int n8 = 0; n8 < 8; n8++) {
            int row0 = m0 + wm + mt * 16 + g;
            int col  = n0 + wn + n8 * 8 + t * 2;
            float c0 = acc[mt][n8][0], c1 = acc[mt][n8][1];
            float c2 = acc[mt][n8][2], c3 = acc[mt][n8][3];
            if (sigm) {
                c0 = 1.f / (1.f + __expf(-c0));
                c1 = 1.f / (1.f + __expf(-c1));
                c2 = 1.f / (1.f + __expf(-c2));
                c3 = 1.f / (1.f + __expf(-c3));
            }
            if (half_out) {
                *(__half2*)(HCo + (size_t)row0 * CC + col)       = __floats2half2_rn(c0, c1);
                *(__half2*)(HCo + (size_t)(row0 + 8) * CC + col) = __floats2half2_rn(c2, c3);
            } else {
                *(float2*)(Co + (size_t)row0 * CC + col)       = make_float2(c0, c1);
                *(float2*)(Co + (size_t)(row0 + 8) * CC + col) = make_float2(c2, c3);
            }
        }
    }
}

// fused k|v|sr: k and sr emitted fp16, v fp32
__global__ __launch_bounds__(256) void gemm3_f16(const __half* __restrict__ A,
                                                 const __half* __restrict__ W,
                                                 __half* __restrict__ Kh,
                                                 float* __restrict__ Vo,
                                                 __half* __restrict__ Sh) {
    extern __shared__ char smem[];
    const int which = blockIdx.x >> 2;
    const int n0 = (blockIdx.x & 3) * 128;
    const int m0 = blockIdx.y * 128;
    float* Co = (which == 1) ? Vo : nullptr;
    __half* HCo = (which == 0) ? Kh : Sh;
    gemm_core(A, W + (size_t)which * CC * CC, Co, HCo, m0, n0,
              which == 2, which != 1, smem);
}

__global__ __launch_bounds__(256) void gemm1_f16(const __half* __restrict__ A,
                                                 const __half* __restrict__ W,
                                                 float* __restrict__ Co) {
    extern __shared__ char smem[];
    gemm_core(A, W, Co, nullptr, blockIdx.y * 128, blockIdx.x * 128, false, false, smem);
}

// ---------------- WKV scans: 2 channels/thread ----------------
#define NCHUNK 64
#define CHL    (TT / NCHUNK)   // 64
#define LPB    8               // lanes per chunk-row (each lane = 2 channels)
#define CHB    (LPB * 2)       // 16 channels per block

__global__ __launch_bounds__(512) void wkv1(const float* __restrict__ decay,
                                            const float* __restrict__ first,
                                            const __half* __restrict__ K,
                                            const float* __restrict__ V,
                                            float* __restrict__ Y) {
    __shared__ float sp[NCHUNK][CHB + 1];
    __shared__ float sq[NCHUNK][CHB + 1];
    __shared__ float so[NCHUNK][CHB + 1];
    const int tid = threadIdx.x;
    const int cl = tid & (LPB - 1);
    const int ch = tid / LPB;
    const int cg = blockIdx.x & 31;        // 32 channel groups
    const int b  = blockIdx.x >> 5;
    const int c0 = cg * CHB + cl * 2;
    const float inv_t = 1.0f / (float)TT;
    const float w0 = decay[c0] * inv_t,     w1 = decay[c0 + 1] * inv_t;
    const float u0 = first[c0] * inv_t,     u1 = first[c0 + 1] * inv_t;
    const size_t base = ((size_t)(b * TT + ch * CHL)) * CC + c0;

    float p0 = 0.f, q0 = 0.f, o0 = -1e38f;
    float p1 = 0.f, q1 = 0.f, o1 = -1e38f;
    #pragma unroll 8
    for (int s = 0; s < CHL; s++) {
        __half2 kh2 = *(const __half2*)(K + base + (size_t)s * CC);
        float2 vv = *(const float2*)(V + base + (size_t)s * CC);
        float2 kk = __half22float2(kh2);
        wkv_step(kk.x, vv.x, w0, p0, q0, o0);
        wkv_step(kk.y, vv.y, w1, p1, q1, o1);
    }
    sp[ch][cl*2] = p0; sq[ch][cl*2] = q0; so[ch][cl*2] = o0;
    sp[ch][cl*2+1] = p1; sq[ch][cl*2+1] = q1; so[ch][cl*2+1] = o1;
    __syncthreads();

    if (ch == 0) {
        #pragma unroll
        for (int half = 0; half < 2; half++) {
            int cc = cl * 2 + half;
            const float Lw = (float)CHL * ((half == 0) ? w0 : w1);
            float ap = 0.f, aq = 0.f, ao = -1e38f;
            #pragma unroll
            for (int i = 0; i < NCHUNK; i++) {
                float tp = sp[i][cc], tq = sq[i][cc], to = so[i][cc];
                sp[i][cc] = ap; sq[i][cc] = aq; so[i][cc] = ao;
                float od = ao + Lw;
                float d  = od - to;
                float e  = __expf(-fabsf(d));
                bool ge  = (d >= 0.f);
                float e1 = ge ? 1.f : e;
                float e2 = ge ? e : 1.f;
                ap = fmaf(e1, ap, e2 * tp);
                aq = fmaf(e1, aq, e2 * tq);
                ao = fmaxf(od, to);
            }
        }
    }
    __syncthreads();
    p0 = sp[ch][cl*2]; q0 = sq[ch][cl*2]; o0 = so[ch][cl*2];
    p1 = sp[ch][cl*2+1]; q1 = sq[ch][cl*2+1]; o1 = so[ch][cl*2+1];

    #pragma unroll 8
    for (int s = 0; s < CHL; s++) {
        size_t idx = base + (size_t)s * CC;
        __half2 kh2 = *(const __half2*)(K + idx);
        float2 vv = *(const float2*)(V + idx);
        float2 kk = __half22float2(kh2);
        float y0 = wkv_out_step(kk.x, vv.x, w0, u0, p0, q0, o0);
        float y1 = wkv_out_step(kk.y, vv.y, w1, u1, p1, q1, o1);
        *(float2*)(Y + idx) = make_float2(y0, y1);
    }
}

// scan 2: zigzag-gathered reads (fused permute); epilogue writes fp16 sr*y.
__global__ __launch_bounds__(512) void wkv2(const float* __restrict__ decay,
                                            const float* __restrict__ first,
                                            const __half* __restrict__ K,
                                            const float* __restrict__ V,
                                            const __half* __restrict__ SR,
                                            __half* __restrict__ Ao) {
    __shared__ float sp[NCHUNK][CHB + 1];
    __shared__ float sq[NCHUNK][CHB + 1];
    __shared__ float so[NCHUNK][CHB + 1];
    const int tid = threadIdx.x;
    const int cl = tid & (LPB - 1);
    const int ch = tid / LPB;              // chunk == image row (CHL == 64 == W)
    const int cg = blockIdx.x & 31;
    const int b  = blockIdx.x >> 5;
    const int c0 = cg * CHB + cl * 2;
    const float inv_t = 1.0f / (float)TT;
    const float w0 = decay[CC + c0] * inv_t,   w1 = decay[CC + c0 + 1] * inv_t;
    const float u0 = first[CC + c0] * inv_t,   u1 = first[CC + c0 + 1] * inv_t;
    const bool rev = (ch & 1);
    const size_t brow = ((size_t)(b << 12) + (ch << 6));

    float p0 = 0.f, q0 = 0.f, o0 = -1e38f;
    float p1 = 0.f, q1 = 0.f, o1 = -1e38f;
    #pragma unroll 8
    for (int s = 0; s < CHL; s++) {
        int col = rev ? (63 - s) : s;
        size_t idx = (brow + col) * CC + c0;
        __half2 kh2 = *(const __half2*)(K + idx);
        float2 vv = *(const float2*)(V + idx);
        float2 kk = __half22float2(kh2);
        wkv_step(kk.x, vv.x, w0, p0, q0, o0);
        wkv_step(kk.y, vv.y, w1, p1, q1, o1);
    }
    sp[ch][cl*2] = p0; sq[ch][cl*2] = q0; so[ch][cl*2] = o0;
    sp[ch][cl*2+1] = p1; sq[ch][cl*2+1] = q1; so[ch][cl*2+1] = o1;
    __syncthreads();

    if (ch == 0) {
        #pragma unroll
        for (int half = 0; half < 2; half++) {
            int cc = cl * 2 + half;
            const float Lw = (float)CHL * ((half == 0) ? w0 : w1);
            float ap = 0.f, aq = 0.f, ao = -1e38f;
            #pragma unroll
            for (int i = 0; i < NCHUNK; i++) {
                float tp = sp[i][cc], tq = sq[i][cc], to = so[i][cc];
                sp[i][cc] = ap; sq[i][cc] = aq; so[i][cc] = ao;
                float od = ao + Lw;
                float d  = od - to;
                float e  = __expf(-fabsf(d));
                bool ge  = (d >= 0.f);
                float e1 = ge ? 1.f : e;
                float e2 = ge ? e : 1.f;
                ap = fmaf(e1, ap, e2 * tp);
                aq = fmaf(e1, aq, e2 * tq);
                ao = fmaxf(od, to);
            }
        }
    }
    __syncthreads();
    p0 = sp[ch][cl*2]; q0 = sq[ch][cl*2]; o0 = so[ch][cl*2];
    p1 = sp[ch][cl*2+1]; q1 = sq[ch][cl*2+1]; o1 = so[ch][cl*2+1];

    #pragma unroll 8
    for (int s = 0; s < CHL; s++) {
        int col = rev ? (63 - s) : s;
        size_t idx = (brow + col) * CC + c0;
        size_t odx = ((size_t)(b * TT + ch * CHL + s)) * CC + c0;
        __half2 kh2 = *(const __half2*)(K + idx);
        float2 vv = *(const float2*)(V + idx);
        float2 kk = __half22float2(kh2);
        float y0 = wkv_out_step(kk.x, vv.x, w0, u0, p0, q0, o0);
        float y1 = wkv_out_step(kk.y, vv.y, w1, u1, p1, q1, o1);
        float2 sr2 = __half22float2(*(const __half2*)(SR + odx));
        *(__half2*)(Ao + odx) = __floats2half2_rn(sr2.x * y0, sr2.y * y1);
    }
}

// ---------------- launch ----------------
extern "C" void kernel_launch(void* const* d_in, const int* in_sizes, int n_in,
                              void* d_out, int out_size) {
    const float* x       = (const float*)d_in[0];
    const float* W_key   = (const float*)d_in[1];
    const float* W_value = (const float*)d_in[2];
    const float* W_recep = (const float*)d_in[3];
    const float* W_out   = (const float*)d_in[4];
    const float* decay   = (const float*)d_in[5];
    const float* first   = (const float*)d_in[6];
    float* out = (float*)d_out;

    float *v;
    __half *kh, *srh, *a, *w;
    cudaGetSymbolAddress((void**)&kh,  g_kh);
    cudaGetSymbolAddress((void**)&v,   g_v);
    cudaGetSymbolAddress((void**)&srh, g_srh);
    cudaGetSymbolAddress((void**)&a,   g_a);
    cudaGetSymbolAddress((void**)&w,   g_w);

    cudaFuncSetAttribute(gemm3_f16, cudaFuncAttributeMaxDynamicSharedMemorySize, SM_TOT);
    cudaFuncSetAttribute(gemm1_f16, cudaFuncAttributeMaxDynamicSharedMemorySize, SM_TOT);

    dim3 eb(256), eg(BTC / 4 / 256);
    dim3 cg(4 * CC * CC / 256);
    dim3 gb(256), gg3(12, GM / 128), gg1(4, GM / 128);
    dim3 wb(512), wg(BB * (CC / CHB));     // 256 blocks

    shift_zigzag_f16<<<eg, eb>>>(x, a);
    conv_w4<<<cg, eb>>>(W_key, W_value, W_recep, W_out, w);
    gemm3_f16<<<gg3, gb, SM_TOT>>>(a, w, kh, v, srh);
    wkv1<<<wg, wb>>>(decay, first, kh, v, v);
    wkv2<<<wg, wb>>>(decay, first, kh, v, srh, a);
    gemm1_f16<<<gg1, gb, SM_TOT>>>(a, w + 3 * (size_t)CC * CC, out);
}

// round 13
// speedup vs baseline: 1.0600x; 1.0600x over previous
#include <cuda_runtime.h>
#include <cuda_fp16.h>
#include <math.h>
#include <stdint.h>

// Fixed problem shape: B=8, H=W=64 -> T=4096, C=512
#define BB   8
#define TT   4096
#define CC   512
#define BTC  (BB*TT*CC)
#define GM   32768
#define GK   512

// ---------------- scratch ----------------
__device__ __half g_kh[BTC];          // k (fp16)
__device__ float  g_v [BTC];          // v -> y1 in place (fp32)
__device__ __half g_srh[BTC];         // sr (fp16)
__device__ __half g_a [BTC];          // GEMM A (xi, then sr*y2), fp16
__device__ __half g_w [4*CC*CC];      // weights, fp16

// ---------------- asm helpers ----------------
__device__ __forceinline__ uint32_t smem_u32(const void* p) {
    uint32_t a;
    asm("{ .reg .u64 t; cvta.to.shared.u64 t, %1; cvt.u32.u64 %0, t; }" : "=r"(a) : "l"(p));
    return a;
}
__device__ __forceinline__ void cp16(uint32_t d, const void* s) {
    asm volatile("cp.async.cg.shared.global [%0], [%1], 16;" :: "r"(d), "l"(s));
}
#define CP_COMMIT() asm volatile("cp.async.commit_group;" ::: "memory")
#define CP_WAIT0()  asm volatile("cp.async.wait_group 0;" ::: "memory")
#define CP_WAIT1()  asm volatile("cp.async.wait_group 1;" ::: "memory")

__device__ __forceinline__ void ldsm4(uint32_t* r, uint32_t a) {
    asm volatile("ldmatrix.sync.aligned.m8n8.x4.shared.b16 {%0,%1,%2,%3}, [%4];"
        : "=r"(r[0]), "=r"(r[1]), "=r"(r[2]), "=r"(r[3]) : "r"(a));
}
__device__ __forceinline__ void mma16816(float* c, const uint32_t* a, const uint32_t* b) {
    asm volatile("mma.sync.aligned.m16n8k16.row.col.f32.f16.f16.f32 "
        "{%0,%1,%2,%3}, {%4,%5,%6,%7}, {%8,%9}, {%0,%1,%2,%3};"
        : "+f"(c[0]), "+f"(c[1]), "+f"(c[2]), "+f"(c[3])
        : "r"(a[0]), "r"(a[1]), "r"(a[2]), "r"(a[3]), "r"(b[0]), "r"(b[1]));
}
#define SW64(o) ((o) ^ (((o) >> 3) & 0x30))

// one WKV recurrence step (state update only)
__device__ __forceinline__ void wkv_step(float kt, float vt, float w,
                                         float& p, float& q, float& o) {
    float wo = w + o;
    float d  = wo - kt;
    float e  = __expf(-fabsf(d));
    bool ge  = (d >= 0.f);
    float A  = ge ? 1.f : e;
    float Bv = ge ? e : 1.f;
    p = fmaf(A, p, Bv * vt);
    q = fmaf(A, q, Bv);
    o = fmaxf(wo, kt);
}
// output + state update
__device__ __forceinline__ float wkv_out_step(float kt, float vt, float w, float u,
                                              float& p, float& q, float& o) {
    float uk = u + kt;
    float d1 = o - uk;
    float e1 = __expf(-fabsf(d1));
    bool g1  = (d1 >= 0.f);
    float A1 = g1 ? 1.f : e1;
    float B1 = g1 ? e1 : 1.f;
    float y  = fmaf(A1, p, B1 * vt) / fmaf(A1, q, B1);
    wkv_step(kt, vt, w, p, q, o);
    return y;
}

// ---------------- kernel 1: q_shift + zigzag -> fp16 ----------------
__global__ void shift_zigzag_f16(const float* __restrict__ x, __half* __restrict__ a) {
    int gid = blockIdx.x * 256 + threadIdx.x;       // float4 units
    int c4 = gid & 127;
    int tp = (gid >> 7) & (TT - 1);
    int b  = gid >> 19;
    int i  = tp >> 6;
    int jj = tp & 63;
    int col = (i & 1) ? (63 - jj) : jj;
    int grp = c4 >> 5;
    int hs = i, ws = col;
    bool valid;
    if (grp == 0)      { ws = col - 1; valid = (col >= 1);  }
    else if (grp == 1) { ws = col + 1; valid = (col <= 62); }
    else if (grp == 2) { hs = i - 1;   valid = (i >= 1);    }
    else               { hs = i + 1;   valid = (i <= 62);   }
    float4 v = make_float4(0.f, 0.f, 0.f, 0.f);
    if (valid)
        v = *(const float4*)(x + ((size_t)((b << 12) + (hs << 6) + ws) << 9) + (c4 << 2));
    __half h[4] = {__float2half_rn(v.x), __float2half_rn(v.y),
                   __float2half_rn(v.z), __float2half_rn(v.w)};
    *(uint2*)(a + ((size_t)gid << 2)) = *(uint2*)h;
}

// ---------------- kernel 2: weight fp16 conversion ----------------
__global__ void conv_w4(const float* __restrict__ w0, const float* __restrict__ w1,
                        const float* __restrict__ w2, const float* __restrict__ w3,
                        __half* __restrict__ wo) {
    int gid = blockIdx.x * 256 + threadIdx.x;
    int sel = gid >> 18;
    int off = gid & (CC * CC - 1);
    const float* src = (sel == 0) ? w0 : (sel == 1) ? w1 : (sel == 2) ? w2 : w3;
    wo[gid] = __float2half_rn(src[off]);
}

// ---------------- GEMM: fp16 1-mma, 128x128 tiles, 3-stage pipe ------
#define TILE_B (128 * 64)
#define STG_B  (2 * TILE_B)        // 16 KB
#define SM_TOT (3 * STG_B)         // 48 KB

__device__ __forceinline__ void gemm_core(const __half* __restrict__ A,
                                          const __half* __restrict__ W,
                                          float* __restrict__ Co,
                                          __half* __restrict__ HCo,
                                          int m0, int n0, bool sigm, bool half_out,
                                          char* smem) {
    const int tid = threadIdx.x;
    const int wid = tid >> 5;
    const int lane = tid & 31;
    const int wm = (wid & 3) * 32;
    const int wn = (wid >> 2) * 64;
    const uint32_t sb0 = smem_u32(smem);

    float acc[2][8][4];
    #pragma unroll
    for (int i = 0; i < 2; i++)
        #pragma unroll
        for (int j = 0; j < 8; j++)
            #pragma unroll
            for (int q = 0; q < 4; q++) acc[i][j][q] = 0.f;

    auto load_stage = [&](int kc, int s) {
        uint32_t sb = sb0 + s * STG_B;
        #pragma unroll
        for (int i = 0; i < 2; i++) {
            int idx = tid + i * 256;
            int r = idx >> 2, c16 = idx & 3;
            uint32_t sw = SW64((uint32_t)(r * 64 + c16 * 16));
            size_t ga = (size_t)(m0 + r) * GK + kc * 32 + c16 * 8;
            size_t gb = (size_t)(n0 + r) * GK + kc * 32 + c16 * 8;
            cp16(sb + sw,          A + ga);
            cp16(sb + TILE_B + sw, W + gb);
        }
    };

    const int sub = lane >> 3, lrow = lane & 7;

    load_stage(0, 0); CP_COMMIT();
    load_stage(1, 1); CP_COMMIT();

    #pragma unroll 1
    for (int kc = 0; kc < 16; kc++) {
        if (kc < 14) { CP_WAIT1(); } else { CP_WAIT0(); }
        __syncthreads();
        if (kc + 2 < 16) {
            int s2 = (kc + 2) % 3;
            load_stage(kc + 2, s2); CP_COMMIT();
        }
        const uint32_t sb = sb0 + (kc % 3) * STG_B;

        #pragma unroll
        for (int k16 = 0; k16 < 2; k16++) {
            const uint32_t kbyte = (uint32_t)(k16 * 32 + (sub >> 1) * 16);
            uint32_t av[2][4], bh[8][2];
            #pragma unroll
            for (int mt = 0; mt < 2; mt++) {
                int row = wm + mt * 16 + (sub & 1) * 8 + lrow;
                uint32_t so = SW64((uint32_t)(row * 64) + kbyte);
                ldsm4(av[mt], sb + so);
            }
            #pragma unroll
            for (int nt = 0; nt < 4; nt++) {
                int row = wn + nt * 16 + (sub & 1) * 8 + lrow;
                uint32_t so = SW64((uint32_t)(row * 64) + kbyte);
                uint32_t t0[4];
                ldsm4(t0, sb + TILE_B + so);
                bh[2*nt][0] = t0[0]; bh[2*nt+1][0] = t0[1];
                bh[2*nt][1] = t0[2]; bh[2*nt+1][1] = t0[3];
            }
            #pragma unroll
            for (int mt = 0; mt < 2; mt++)
                #pragma unroll
                for (int n8 = 0; n8 < 8; n8++)
                    mma16816(acc[mt][n8], av[mt], bh[n8]);
        }
    }

    const int g = lane >> 2, t = lane & 3;
    #pragma unroll
    for (int mt = 0; mt < 2; mt++) {
        #pragma unroll
        for (int n8 = 0; n8 < 8; n8++) {
            int row0 = m0 + wm + mt * 16 + g;
            int col  = n0 + wn + n8 * 8 + t * 2;
            float c0 = acc[mt][n8][0], c1 = acc[mt][n8][1];
            float c2 = acc[mt][n8][2], c3 = acc[mt][n8][3];
            if (sigm) {
                c0 = 1.f / (1.f + __expf(-c0));
                c1 = 1.f / (1.f + __expf(-c1));
                c2 = 1.f / (1.f + __expf(-c2));
                c3 = 1.f / (1.f + __expf(-c3));
            }
            if (half_out) {
                *(__half2*)(HCo + (size_t)row0 * CC + col)       = __floats2half2_rn(c0, c1);
                *(__half2*)(HCo + (size_t)(row0 + 8) * CC + col) = __floats2half2_rn(c2, c3);
            } else {
                *(float2*)(Co + (size_t)row0 * CC + col)       = make_float2(c0, c1);
                *(float2*)(Co + (size_t)(row0 + 8) * CC + col) = make_float2(c2, c3);
            }
        }
    }
}

// fused k|v|sr: k and sr emitted fp16, v fp32
__global__ __launch_bounds__(256) void gemm3_f16(const __half* __restrict__ A,
                                                 const __half* __restrict__ W,
                                                 __half* __restrict__ Kh,
                                                 float* __restrict__ Vo,
                                                 __half* __restrict__ Sh) {
    extern __shared__ char smem[];
    const int which = blockIdx.x >> 2;
    const int n0 = (blockIdx.x & 3) * 128;
    const int m0 = blockIdx.y * 128;
    float* Co = (which == 1) ? Vo : nullptr;
    __half* HCo = (which == 0) ? Kh : Sh;
    gemm_core(A, W + (size_t)which * CC * CC, Co, HCo, m0, n0,
              which == 2, which != 1, smem);
}

__global__ __launch_bounds__(256) void gemm1_f16(const __half* __restrict__ A,
                                                 const __half* __restrict__ W,
                                                 float* __restrict__ Co) {
    extern __shared__ char smem[];
    gemm_core(A, W, Co, nullptr, blockIdx.y * 128, blockIdx.x * 128, false, false, smem);
}

// ---------------- WKV scans: 2 ch/thread, 128 chunks of 32, 1024 thr ----------
#define NCHUNK 128
#define CHL    (TT / NCHUNK)   // 32
#define LPB    8               // lanes per chunk-row (each lane = 2 channels)
#define CHB    (LPB * 2)       // 16 channels per block

__global__ __launch_bounds__(1024) void wkv1(const float* __restrict__ decay,
                                             const float* __restrict__ first,
                                             const __half* __restrict__ K,
                                             const float* __restrict__ V,
                                             float* __restrict__ Y) {
    __shared__ float sp[NCHUNK][CHB + 1];
    __shared__ float sq[NCHUNK][CHB + 1];
    __shared__ float so[NCHUNK][CHB + 1];
    const int tid = threadIdx.x;
    const int cl = tid & (LPB - 1);
    const int ch = tid / LPB;              // chunk 0..127
    const int cg = blockIdx.x & 31;        // 32 channel groups
    const int b  = blockIdx.x >> 5;
    const int c0 = cg * CHB + cl * 2;
    const float inv_t = 1.0f / (float)TT;
    const float w0 = decay[c0] * inv_t,     w1 = decay[c0 + 1] * inv_t;
    const float u0 = first[c0] * inv_t,     u1 = first[c0 + 1] * inv_t;
    const size_t base = ((size_t)(b * TT + ch * CHL)) * CC + c0;

    float p0 = 0.f, q0 = 0.f, o0 = -1e38f;
    float p1 = 0.f, q1 = 0.f, o1 = -1e38f;
    #pragma unroll 8
    for (int s = 0; s < CHL; s++) {
        __half2 kh2 = *(const __half2*)(K + base + (size_t)s * CC);
        float2 vv = *(const float2*)(V + base + (size_t)s * CC);
        float2 kk = __half22float2(kh2);
        wkv_step(kk.x, vv.x, w0, p0, q0, o0);
        wkv_step(kk.y, vv.y, w1, p1, q1, o1);
    }
    sp[ch][cl*2] = p0; sq[ch][cl*2] = q0; so[ch][cl*2] = o0;
    sp[ch][cl*2+1] = p1; sq[ch][cl*2+1] = q1; so[ch][cl*2+1] = o1;
    __syncthreads();

    // exclusive prefix over chunks: 16 threads (ch<2), one channel each
    if (ch < 2) {
        int cc = cl * 2 + ch;
        const float Lw = (float)CHL * ((ch == 0) ? w0 : w1);
        float ap = 0.f, aq = 0.f, ao = -1e38f;
        #pragma unroll 8
        for (int i = 0; i < NCHUNK; i++) {
            float tp = sp[i][cc], tq = sq[i][cc], to = so[i][cc];
            sp[i][cc] = ap; sq[i][cc] = aq; so[i][cc] = ao;
            float od = ao + Lw;
            float d  = od - to;
            float e  = __expf(-fabsf(d));
            bool ge  = (d >= 0.f);
            float e1 = ge ? 1.f : e;
            float e2 = ge ? e : 1.f;
            ap = fmaf(e1, ap, e2 * tp);
            aq = fmaf(e1, aq, e2 * tq);
            ao = fmaxf(od, to);
        }
    }
    __syncthreads();
    p0 = sp[ch][cl*2]; q0 = sq[ch][cl*2]; o0 = so[ch][cl*2];
    p1 = sp[ch][cl*2+1]; q1 = sq[ch][cl*2+1]; o1 = so[ch][cl*2+1];

    #pragma unroll 8
    for (int s = 0; s < CHL; s++) {
        size_t idx = base + (size_t)s * CC;
        __half2 kh2 = *(const __half2*)(K + idx);
        float2 vv = *(const float2*)(V + idx);
        float2 kk = __half22float2(kh2);
        float y0 = wkv_out_step(kk.x, vv.x, w0, u0, p0, q0, o0);
        float y1 = wkv_out_step(kk.y, vv.y, w1, u1, p1, q1, o1);
        *(float2*)(Y + idx) = make_float2(y0, y1);
    }
}

// scan 2: zigzag-gathered reads (fused permute); epilogue writes fp16 sr*y.
__global__ __launch_bounds__(1024) void wkv2(const float* __restrict__ decay,
                                             const float* __restrict__ first,
                                             const __half* __restrict__ K,
                                             const float* __restrict__ V,
                                             const __half* __restrict__ SR,
                                             __half* __restrict__ Ao) {
    __shared__ float sp[NCHUNK][CHB + 1];
    __shared__ float sq[NCHUNK][CHB + 1];
    __shared__ float so[NCHUNK][CHB + 1];
    const int tid = threadIdx.x;
    const int cl = tid & (LPB - 1);
    const int ch = tid / LPB;              // chunk 0..127 (half image row)
    const int cg = blockIdx.x & 31;
    const int b  = blockIdx.x >> 5;
    const int c0 = cg * CHB + cl * 2;
    const float inv_t = 1.0f / (float)TT;
    const float w0 = decay[CC + c0] * inv_t,   w1 = decay[CC + c0 + 1] * inv_t;
    const float u0 = first[CC + c0] * inv_t,   u1 = first[CC + c0 + 1] * inv_t;
    const int irow = ch >> 1;              // image row
    const int jbase = (ch & 1) << 5;       // 0 or 32 within the row's zigzag order
    const bool rev = (irow & 1);
    const size_t brow = ((size_t)(b << 12) + (irow << 6));

    float p0 = 0.f, q0 = 0.f, o0 = -1e38f;
    float p1 = 0.f, q1 = 0.f, o1 = -1e38f;
    #pragma unroll 8
    for (int s = 0; s < CHL; s++) {
        int jj = jbase + s;
        int col = rev ? (63 - jj) : jj;
        size_t idx = (brow + col) * CC + c0;
        __half2 kh2 = *(const __half2*)(K + idx);
        float2 vv = *(const float2*)(V + idx);
        float2 kk = __half22float2(kh2);
        wkv_step(kk.x, vv.x, w0, p0, q0, o0);
        wkv_step(kk.y, vv.y, w1, p1, q1, o1);
    }
    sp[ch][cl*2] = p0; sq[ch][cl*2] = q0; so[ch][cl*2] = o0;
    sp[ch][cl*2+1] = p1; sq[ch][cl*2+1] = q1; so[ch][cl*2+1] = o1;
    __syncthreads();

    if (ch < 2) {
        int cc = cl * 2 + ch;
        const float Lw = (float)CHL * ((ch == 0) ? w0 : w1);
        float ap = 0.f, aq = 0.f, ao = -1e38f;
        #pragma unroll 8
        for (int i = 0; i < NCHUNK; i++) {
            float tp = sp[i][cc], tq = sq[i][cc], to = so[i][cc];
            sp[i][cc] = ap; sq[i][cc] = aq; so[i][cc] = ao;
            float od = ao + Lw;
            float d  = od - to;
            float e  = __expf(-fabsf(d));
            bool ge  = (d >= 0.f);
            float e1 = ge ? 1.f : e;
            float e2 = ge ? e : 1.f;
            ap = fmaf(e1, ap, e2 * tp);
            aq = fmaf(e1, aq, e2 * tq);
            ao = fmaxf(od, to);
        }
    }
    __syncthreads();
    p0 = sp[ch][cl*2]; q0 = sq[ch][cl*2]; o0 = so[ch][cl*2];
    p1 = sp[ch][cl*2+1]; q1 = sq[ch][cl*2+1]; o1 = so[ch][cl*2+1];

    #pragma unroll 8
    for (int s = 0; s < CHL; s++) {
        int jj = jbase + s;
        int col = rev ? (63 - jj) : jj;
        size_t idx = (brow + col) * CC + c0;
        size_t odx = ((size_t)(b * TT + ch * CHL + s)) * CC + c0;
        __half2 kh2 = *(const __half2*)(K + idx);
        float2 vv = *(const float2*)(V + idx);
        float2 kk = __half22float2(kh2);
        float y0 = wkv_out_step(kk.x, vv.x, w0, u0, p0, q0, o0);
        float y1 = wkv_out_step(kk.y, vv.y, w1, u1, p1, q1, o1);
        float2 sr2 = __half22float2(*(const __half2*)(SR + odx));
        *(__half2*)(Ao + odx) = __floats2half2_rn(sr2.x * y0, sr2.y * y1);
    }
}

// ---------------- launch ----------------
extern "C" void kernel_launch(void* const* d_in, const int* in_sizes, int n_in,
                              void* d_out, int out_size) {
    const float* x       = (const float*)d_in[0];
    const float* W_key   = (const float*)d_in[1];
    const float* W_value = (const float*)d_in[2];
    const float* W_recep = (const float*)d_in[3];
    const float* W_out   = (const float*)d_in[4];
    const float* decay   = (const float*)d_in[5];
    const float* first   = (const float*)d_in[6];
    float* out = (float*)d_out;

    float *v;
    __half *kh, *srh, *a, *w;
    cudaGetSymbolAddress((void**)&kh,  g_kh);
    cudaGetSymbolAddress((void**)&v,   g_v);
    cudaGetSymbolAddress((void**)&srh, g_srh);
    cudaGetSymbolAddress((void**)&a,   g_a);
    cudaGetSymbolAddress((void**)&w,   g_w);

    cudaFuncSetAttribute(gemm3_f16, cudaFuncAttributeMaxDynamicSharedMemorySize, SM_TOT);
    cudaFuncSetAttribute(gemm1_f16, cudaFuncAttributeMaxDynamicSharedMemorySize, SM_TOT);

    dim3 eb(256), eg(BTC / 4 / 256);
    dim3 cg(4 * CC * CC / 256);
    dim3 gb(256), gg3(12, GM / 128), gg1(4, GM / 128);
    dim3 wb(1024), wg(BB * (CC / CHB));    // 256 blocks

    shift_zigzag_f16<<<eg, eb>>>(x, a);
    conv_w4<<<cg, eb>>>(W_key, W_value, W_recep, W_out, w);
    gemm3_f16<<<gg3, gb, SM_TOT>>>(a, w, kh, v, srh);
    wkv1<<<wg, wb>>>(decay, first, kh, v, v);
    wkv2<<<wg, wb>>>(decay, first, kh, v, srh, a);
    gemm1_f16<<<gg1, gb, SM_TOT>>>(a, w + 3 * (size_t)CC * CC, out);
}

// round 14
// speedup vs baseline: 1.0805x; 1.0193x over previous
#include <cuda_runtime.h>
#include <cuda_fp16.h>
#include <math.h>
#include <stdint.h>

// Fixed problem shape: B=8, H=W=64 -> T=4096, C=512
#define BB   8
#define TT   4096
#define CC   512
#define BTC  (BB*TT*CC)
#define GM   32768
#define GK   512

// ---------------- scratch ----------------
__device__ __half g_kh[BTC];          // k (fp16)
__device__ __half g_vh[BTC];          // v -> y1 in place (fp16)
__device__ __half g_srh[BTC];         // sr (fp16)
__device__ __half g_a [BTC];          // GEMM A (xi, then sr*y2), fp16
__device__ __half g_w [4*CC*CC];      // weights, fp16

// ---------------- asm helpers ----------------
__device__ __forceinline__ uint32_t smem_u32(const void* p) {
    uint32_t a;
    asm("{ .reg .u64 t; cvta.to.shared.u64 t, %1; cvt.u32.u64 %0, t; }" : "=r"(a) : "l"(p));
    return a;
}
__device__ __forceinline__ void cp16(uint32_t d, const void* s) {
    asm volatile("cp.async.cg.shared.global [%0], [%1], 16;" :: "r"(d), "l"(s));
}
#define CP_COMMIT() asm volatile("cp.async.commit_group;" ::: "memory")
#define CP_WAIT0()  asm volatile("cp.async.wait_group 0;" ::: "memory")
#define CP_WAIT1()  asm volatile("cp.async.wait_group 1;" ::: "memory")

__device__ __forceinline__ void ldsm4(uint32_t* r, uint32_t a) {
    asm volatile("ldmatrix.sync.aligned.m8n8.x4.shared.b16 {%0,%1,%2,%3}, [%4];"
        : "=r"(r[0]), "=r"(r[1]), "=r"(r[2]), "=r"(r[3]) : "r"(a));
}
__device__ __forceinline__ void mma16816(float* c, const uint32_t* a, const uint32_t* b) {
    asm volatile("mma.sync.aligned.m16n8k16.row.col.f32.f16.f16.f32 "
        "{%0,%1,%2,%3}, {%4,%5,%6,%7}, {%8,%9}, {%0,%1,%2,%3};"
        : "+f"(c[0]), "+f"(c[1]), "+f"(c[2]), "+f"(c[3])
        : "r"(a[0]), "r"(a[1]), "r"(a[2]), "r"(a[3]), "r"(b[0]), "r"(b[1]));
}
#define SW64(o) ((o) ^ (((o) >> 3) & 0x30))

// one WKV recurrence step (state update only)
__device__ __forceinline__ void wkv_step(float kt, float vt, float w,
                                         float& p, float& q, float& o) {
    float wo = w + o;
    float d  = wo - kt;
    float e  = __expf(-fabsf(d));
    bool ge  = (d >= 0.f);
    float A  = ge ? 1.f : e;
    float Bv = ge ? e : 1.f;
    p = fmaf(A, p, Bv * vt);
    q = fmaf(A, q, Bv);
    o = fmaxf(wo, kt);
}
// output + state update
__device__ __forceinline__ float wkv_out_step(float kt, float vt, float w, float u,
                                              float& p, float& q, float& o) {
    float uk = u + kt;
    float d1 = o - uk;
    float e1 = __expf(-fabsf(d1));
    bool g1  = (d1 >= 0.f);
    float A1 = g1 ? 1.f : e1;
    float B1 = g1 ? e1 : 1.f;
    float y  = fmaf(A1, p, B1 * vt) / fmaf(A1, q, B1);
    wkv_step(kt, vt, w, p, q, o);
    return y;
}

// ---------------- kernel 1: q_shift + zigzag -> fp16 ----------------
__global__ void shift_zigzag_f16(const float* __restrict__ x, __half* __restrict__ a) {
    int gid = blockIdx.x * 256 + threadIdx.x;       // float4 units
    int c4 = gid & 127;
    int tp = (gid >> 7) & (TT - 1);
    int b  = gid >> 19;
    int i  = tp >> 6;
    int jj = tp & 63;
    int col = (i & 1) ? (63 - jj) : jj;
    int grp = c4 >> 5;
    int hs = i, ws = col;
    bool valid;
    if (grp == 0)      { ws = col - 1; valid = (col >= 1);  }
    else if (grp == 1) { ws = col + 1; valid = (col <= 62); }
    else if (grp == 2) { hs = i - 1;   valid = (i >= 1);    }
    else               { hs = i + 1;   valid = (i <= 62);   }
    float4 v = make_float4(0.f, 0.f, 0.f, 0.f);
    if (valid)
        v = *(const float4*)(x + ((size_t)((b << 12) + (hs << 6) + ws) << 9) + (c4 << 2));
    __half h[4] = {__float2half_rn(v.x), __float2half_rn(v.y),
                   __float2half_rn(v.z), __float2half_rn(v.w)};
    *(uint2*)(a + ((size_t)gid << 2)) = *(uint2*)h;
}

// ---------------- kernel 2: weight fp16 conversion ----------------
__global__ void conv_w4(const float* __restrict__ w0, const float* __restrict__ w1,
                        const float* __restrict__ w2, const float* __restrict__ w3,
                        __half* __restrict__ wo) {
    int gid = blockIdx.x * 256 + threadIdx.x;
    int sel = gid >> 18;
    int off = gid & (CC * CC - 1);
    const float* src = (sel == 0) ? w0 : (sel == 1) ? w1 : (sel == 2) ? w2 : w3;
    wo[gid] = __float2half_rn(src[off]);
}

// ---------------- GEMM: fp16 1-mma, 128x128 tiles, 3-stage pipe ------
#define TILE_B (128 * 64)
#define STG_B  (2 * TILE_B)        // 16 KB
#define SM_TOT (3 * STG_B)         // 48 KB

__device__ __forceinline__ void gemm_core(const __half* __restrict__ A,
                                          const __half* __restrict__ W,
                                          float* __restrict__ Co,
                                          __half* __restrict__ HCo,
                                          int m0, int n0, bool sigm, bool half_out,
                                          char* smem) {
    const int tid = threadIdx.x;
    const int wid = tid >> 5;
    const int lane = tid & 31;
    const int wm = (wid & 3) * 32;
    const int wn = (wid >> 2) * 64;
    const uint32_t sb0 = smem_u32(smem);

    float acc[2][8][4];
    #pragma unroll
    for (int i = 0; i < 2; i++)
        #pragma unroll
        for (int j = 0; j < 8; j++)
            #pragma unroll
            for (int q = 0; q < 4; q++) acc[i][j][q] = 0.f;

    auto load_stage = [&](int kc, int s) {
        uint32_t sb = sb0 + s * STG_B;
        #pragma unroll
        for (int i = 0; i < 2; i++) {
            int idx = tid + i * 256;
            int r = idx >> 2, c16 = idx & 3;
            uint32_t sw = SW64((uint32_t)(r * 64 + c16 * 16));
            size_t ga = (size_t)(m0 + r) * GK + kc * 32 + c16 * 8;
            size_t gb = (size_t)(n0 + r) * GK + kc * 32 + c16 * 8;
            cp16(sb + sw,          A + ga);
            cp16(sb + TILE_B + sw, W + gb);
        }
    };

    const int sub = lane >> 3, lrow = lane & 7;

    load_stage(0, 0); CP_COMMIT();
    load_stage(1, 1); CP_COMMIT();

    #pragma unroll 1
    for (int kc = 0; kc < 16; kc++) {
        if (kc < 14) { CP_WAIT1(); } else { CP_WAIT0(); }
        __syncthreads();
        if (kc + 2 < 16) {
            int s2 = (kc + 2) % 3;
            load_stage(kc + 2, s2); CP_COMMIT();
        }
        const uint32_t sb = sb0 + (kc % 3) * STG_B;

        #pragma unroll
        for (int k16 = 0; k16 < 2; k16++) {
            const uint32_t kbyte = (uint32_t)(k16 * 32 + (sub >> 1) * 16);
            uint32_t av[2][4], bh[8][2];
            #pragma unroll
            for (int mt = 0; mt < 2; mt++) {
                int row = wm + mt * 16 + (sub & 1) * 8 + lrow;
                uint32_t so = SW64((uint32_t)(row * 64) + kbyte);
                ldsm4(av[mt], sb + so);
            }
            #pragma unroll
            for (int nt = 0; nt < 4; nt++) {
                int row = wn + nt * 16 + (sub & 1) * 8 + lrow;
                uint32_t so = SW64((uint32_t)(row * 64) + kbyte);
                uint32_t t0[4];
                ldsm4(t0, sb + TILE_B + so);
                bh[2*nt][0] = t0[0]; bh[2*nt+1][0] = t0[1];
                bh[2*nt][1] = t0[2]; bh[2*nt+1][1] = t0[3];
            }
            #pragma unroll
            for (int mt = 0; mt < 2; mt++)
                #pragma unroll
                for (int n8 = 0; n8 < 8; n8++)
                    mma16816(acc[mt][n8], av[mt], bh[n8]);
        }
    }

    const int g = lane >> 2, t = lane & 3;
    #pragma unroll
    for (int mt = 0; mt < 2; mt++) {
        #pragma unroll
        for (int n8 = 0; n8 < 8; n8++) {
            int row0 = m0 + wm + mt * 16 + g;
            int col  = n0 + wn + n8 * 8 + t * 2;
            float c0 = acc[mt][n8][0], c1 = acc[mt][n8][1];
            float c2 = acc[mt][n8][2], c3 = acc[mt][n8][3];
            if (sigm) {
                c0 = 1.f / (1.f + __expf(-c0));
                c1 = 1.f / (1.f + __expf(-c1));
                c2 = 1.f / (1.f + __expf(-c2));
                c3 = 1.f / (1.f + __expf(-c3));
            }
            if (half_out) {
                *(__half2*)(HCo + (size_t)row0 * CC + col)       = __floats2half2_rn(c0, c1);
                *(__half2*)(HCo + (size_t)(row0 + 8) * CC + col) = __floats2half2_rn(c2, c3);
            } else {
                *(float2*)(Co + (size_t)row0 * CC + col)       = make_float2(c0, c1);
                *(float2*)(Co + (size_t)(row0 + 8) * CC + col) = make_float2(c2, c3);
            }
        }
    }
}

// fused k|v|sr: all three emitted fp16
__global__ __launch_bounds__(256) void gemm3_f16(const __half* __restrict__ A,
                                                 const __half* __restrict__ W,
                                                 __half* __restrict__ Kh,
                                                 __half* __restrict__ Vh,
                                                 __half* __restrict__ Sh) {
    extern __shared__ char smem[];
    const int which = blockIdx.x >> 2;
    const int n0 = (blockIdx.x & 3) * 128;
    const int m0 = blockIdx.y * 128;
    __half* HCo = (which == 0) ? Kh : (which == 1) ? Vh : Sh;
    gemm_core(A, W + (size_t)which * CC * CC, nullptr, HCo, m0, n0,
              which == 2, true, smem);
}

__global__ __launch_bounds__(256) void gemm1_f16(const __half* __restrict__ A,
                                                 const __half* __restrict__ W,
                                                 float* __restrict__ Co) {
    extern __shared__ char smem[];
    gemm_core(A, W, Co, nullptr, blockIdx.y * 128, blockIdx.x * 128, false, false, smem);
}

// ---------------- WKV scans: 2 ch/thread, 128 chunks of 32, 1024 thr ----------
#define NCHUNK 128
#define CHL    (TT / NCHUNK)   // 32
#define LPB    8               // lanes per chunk-row (each lane = 2 channels)
#define CHB    (LPB * 2)       // 16 channels per block

__global__ __launch_bounds__(1024) void wkv1(const float* __restrict__ decay,
                                             const float* __restrict__ first,
                                             const __half* __restrict__ K,
                                             const __half* __restrict__ V,
                                             __half* __restrict__ Y) {
    __shared__ float sp[NCHUNK][CHB + 1];
    __shared__ float sq[NCHUNK][CHB + 1];
    __shared__ float so[NCHUNK][CHB + 1];
    const int tid = threadIdx.x;
    const int cl = tid & (LPB - 1);
    const int ch = tid / LPB;              // chunk 0..127
    const int cg = blockIdx.x & 31;        // 32 channel groups
    const int b  = blockIdx.x >> 5;
    const int c0 = cg * CHB + cl * 2;
    const float inv_t = 1.0f / (float)TT;
    const float w0 = decay[c0] * inv_t,     w1 = decay[c0 + 1] * inv_t;
    const float u0 = first[c0] * inv_t,     u1 = first[c0 + 1] * inv_t;
    const size_t base = ((size_t)(b * TT + ch * CHL)) * CC + c0;

    float p0 = 0.f, q0 = 0.f, o0 = -1e38f;
    float p1 = 0.f, q1 = 0.f, o1 = -1e38f;
    #pragma unroll 8
    for (int s = 0; s < CHL; s++) {
        float2 kk = __half22float2(*(const __half2*)(K + base + (size_t)s * CC));
        float2 vv = __half22float2(*(const __half2*)(V + base + (size_t)s * CC));
        wkv_step(kk.x, vv.x, w0, p0, q0, o0);
        wkv_step(kk.y, vv.y, w1, p1, q1, o1);
    }
    sp[ch][cl*2] = p0; sq[ch][cl*2] = q0; so[ch][cl*2] = o0;
    sp[ch][cl*2+1] = p1; sq[ch][cl*2+1] = q1; so[ch][cl*2+1] = o1;
    __syncthreads();

    // exclusive prefix over chunks: 16 threads (ch<2), one channel each
    if (ch < 2) {
        int cc = cl * 2 + ch;
        const float Lw = (float)CHL * ((ch == 0) ? w0 : w1);
        float ap = 0.f, aq = 0.f, ao = -1e38f;
        #pragma unroll 8
        for (int i = 0; i < NCHUNK; i++) {
            float tp = sp[i][cc], tq = sq[i][cc], to = so[i][cc];
            sp[i][cc] = ap; sq[i][cc] = aq; so[i][cc] = ao;
            float od = ao + Lw;
            float d  = od - to;
            float e  = __expf(-fabsf(d));
            bool ge  = (d >= 0.f);
            float e1 = ge ? 1.f : e;
            float e2 = ge ? e : 1.f;
            ap = fmaf(e1, ap, e2 * tp);
            aq = fmaf(e1, aq, e2 * tq);
            ao = fmaxf(od, to);
        }
    }
    __syncthreads();
    p0 = sp[ch][cl*2]; q0 = sq[ch][cl*2]; o0 = so[ch][cl*2];
    p1 = sp[ch][cl*2+1]; q1 = sq[ch][cl*2+1]; o1 = so[ch][cl*2+1];

    #pragma unroll 8
    for (int s = 0; s < CHL; s++) {
        size_t idx = base + (size_t)s * CC;
        float2 kk = __half22float2(*(const __half2*)(K + idx));
        float2 vv = __half22float2(*(const __half2*)(V + idx));
        float y0 = wkv_out_step(kk.x, vv.x, w0, u0, p0, q0, o0);
        float y1 = wkv_out_step(kk.y, vv.y, w1, u1, p1, q1, o1);
        *(__half2*)(Y + idx) = __floats2half2_rn(y0, y1);
    }
}

// scan 2: zigzag-gathered reads (fused permute); epilogue writes fp16 sr*y.
__global__ __launch_bounds__(1024) void wkv2(const float* __restrict__ decay,
                                             const float* __restrict__ first,
                                             const __half* __restrict__ K,
                                             const __half* __restrict__ V,
                                             const __half* __restrict__ SR,
                                             __half* __restrict__ Ao) {
    __shared__ float sp[NCHUNK][CHB + 1];
    __shared__ float sq[NCHUNK][CHB + 1];
    __shared__ float so[NCHUNK][CHB + 1];
    const int tid = threadIdx.x;
    const int cl = tid & (LPB - 1);
    const int ch = tid / LPB;              // chunk 0..127 (half image row)
    const int cg = blockIdx.x & 31;
    const int b  = blockIdx.x >> 5;
    const int c0 = cg * CHB + cl * 2;
    const float inv_t = 1.0f / (float)TT;
    const float w0 = decay[CC + c0] * inv_t,   w1 = decay[CC + c0 + 1] * inv_t;
    const float u0 = first[CC + c0] * inv_t,   u1 = first[CC + c0 + 1] * inv_t;
    const int irow = ch >> 1;              // image row
    const int jbase = (ch & 1) << 5;       // 0 or 32 within the row's zigzag order
    const bool rev = (irow & 1);
    const size_t brow = ((size_t)(b << 12) + (irow << 6));

    float p0 = 0.f, q0 = 0.f, o0 = -1e38f;
    float p1 = 0.f, q1 = 0.f, o1 = -1e38f;
    #pragma unroll 8
    for (int s = 0; s < CHL; s++) {
        int jj = jbase + s;
        int col = rev ? (63 - jj) : jj;
        size_t idx = (brow + col) * CC + c0;
        float2 kk = __half22float2(*(const __half2*)(K + idx));
        float2 vv = __half22float2(*(const __half2*)(V + idx));
        wkv_step(kk.x, vv.x, w0, p0, q0, o0);
        wkv_step(kk.y, vv.y, w1, p1, q1, o1);
    }
    sp[ch][cl*2] = p0; sq[ch][cl*2] = q0; so[ch][cl*2] = o0;
    sp[ch][cl*2+1] = p1; sq[ch][cl*2+1] = q1; so[ch][cl*2+1] = o1;
    __syncthreads();

    if (ch < 2) {
        int cc = cl * 2 + ch;
        const float Lw = (float)CHL * ((ch == 0) ? w0 : w1);
        float ap = 0.f, aq = 0.f, ao = -1e38f;
        #pragma unroll 8
        for (int i = 0; i < NCHUNK; i++) {
            float tp = sp[i][cc], tq = sq[i][cc], to = so[i][cc];
            sp[i][cc] = ap; sq[i][cc] = aq; so[i][cc] = ao;
            float od = ao + Lw;
            float d  = od - to;
            float e  = __expf(-fabsf(d));
            bool ge  = (d >= 0.f);
            float e1 = ge ? 1.f : e;
            float e2 = ge ? e : 1.f;
            ap = fmaf(e1, ap, e2 * tp);
            aq = fmaf(e1, aq, e2 * tq);
            ao = fmaxf(od, to);
        }
    }
    __syncthreads();
    p0 = sp[ch][cl*2]; q0 = sq[ch][cl*2]; o0 = so[ch][cl*2];
    p1 = sp[ch][cl*2+1]; q1 = sq[ch][cl*2+1]; o1 = so[ch][cl*2+1];

    #pragma unroll 8
    for (int s = 0; s < CHL; s++) {
        int jj = jbase + s;
        int col = rev ? (63 - jj) : jj;
        size_t idx = (brow + col) * CC + c0;
        size_t odx = ((size_t)(b * TT + ch * CHL + s)) * CC + c0;
        float2 kk = __half22float2(*(const __half2*)(K + idx));
        float2 vv = __half22float2(*(const __half2*)(V + idx));
        float y0 = wkv_out_step(kk.x, vv.x, w0, u0, p0, q0, o0);
        float y1 = wkv_out_step(kk.y, vv.y, w1, u1, p1, q1, o1);
        float2 sr2 = __half22float2(*(const __half2*)(SR + odx));
        *(__half2*)(Ao + odx) = __floats2half2_rn(sr2.x * y0, sr2.y * y1);
    }
}

// ---------------- launch ----------------
extern "C" void kernel_launch(void* const* d_in, const int* in_sizes, int n_in,
                              void* d_out, int out_size) {
    const float* x       = (const float*)d_in[0];
    const float* W_key   = (const float*)d_in[1];
    const float* W_value = (const float*)d_in[2];
    const float* W_recep = (const float*)d_in[3];
    const float* W_out   = (const float*)d_in[4];
    const float* decay   = (const float*)d_in[5];
    const float* first   = (const float*)d_in[6];
    float* out = (float*)d_out;

    __half *kh, *vh, *srh, *a, *w;
    cudaGetSymbolAddress((void**)&kh,  g_kh);
    cudaGetSymbolAddress((void**)&vh,  g_vh);
    cudaGetSymbolAddress((void**)&srh, g_srh);
    cudaGetSymbolAddress((void**)&a,   g_a);
    cudaGetSymbolAddress((void**)&w,   g_w);

    cudaFuncSetAttribute(gemm3_f16, cudaFuncAttributeMaxDynamicSharedMemorySize, SM_TOT);
    cudaFuncSetAttribute(gemm1_f16, cudaFuncAttributeMaxDynamicSharedMemorySize, SM_TOT);

    dim3 eb(256), eg(BTC / 4 / 256);
    dim3 cg(4 * CC * CC / 256);
    dim3 gb(256), gg3(12, GM / 128), gg1(4, GM / 128);
    dim3 wb(1024), wg(BB * (CC / CHB));    // 256 blocks

    shift_zigzag_f16<<<eg, eb>>>(x, a);
    conv_w4<<<cg, eb>>>(W_key, W_value, W_recep, W_out, w);
    gemm3_f16<<<gg3, gb, SM_TOT>>>(a, w, kh, vh, srh);
    wkv1<<<wg, wb>>>(decay, first, kh, vh, vh);
    wkv2<<<wg, wb>>>(decay, first, kh, vh, srh, a);
    gemm1_f16<<<gg1, gb, SM_TOT>>>(a, w + 3 * (size_t)CC * CC, out);
}

// round 15
// speedup vs baseline: 1.0986x; 1.0168x over previous
#include <cuda_runtime.h>
#include <cuda_fp16.h>
#include <math.h>
#include <stdint.h>

// Fixed problem shape: B=8, H=W=64 -> T=4096, C=512
#define BB   8
#define TT   4096
#define CC   512
#define BTC  (BB*TT*CC)
#define GM   32768
#define GK   512

// ---------------- scratch ----------------
__device__ __half g_kh[BTC];          // k (fp16)
__device__ __half g_vh[BTC];          // v -> y1 in place (fp16)
__device__ __half g_srh[BTC];         // sr (fp16)
__device__ __half g_a [BTC];          // GEMM A (xi, then sr*y2), fp16
__device__ __half g_w [4*CC*CC];      // weights, fp16

// ---------------- asm helpers ----------------
__device__ __forceinline__ uint32_t smem_u32(const void* p) {
    uint32_t a;
    asm("{ .reg .u64 t; cvta.to.shared.u64 t, %1; cvt.u32.u64 %0, t; }" : "=r"(a) : "l"(p));
    return a;
}
__device__ __forceinline__ void cp16(uint32_t d, const void* s) {
    asm volatile("cp.async.cg.shared.global [%0], [%1], 16;" :: "r"(d), "l"(s));
}
#define CP_COMMIT() asm volatile("cp.async.commit_group;" ::: "memory")
#define CP_WAIT0()  asm volatile("cp.async.wait_group 0;" ::: "memory")
#define CP_WAIT1()  asm volatile("cp.async.wait_group 1;" ::: "memory")

__device__ __forceinline__ void ldsm4(uint32_t* r, uint32_t a) {
    asm volatile("ldmatrix.sync.aligned.m8n8.x4.shared.b16 {%0,%1,%2,%3}, [%4];"
        : "=r"(r[0]), "=r"(r[1]), "=r"(r[2]), "=r"(r[3]) : "r"(a));
}
__device__ __forceinline__ void mma16816(float* c, const uint32_t* a, const uint32_t* b) {
    asm volatile("mma.sync.aligned.m16n8k16.row.col.f32.f16.f16.f32 "
        "{%0,%1,%2,%3}, {%4,%5,%6,%7}, {%8,%9}, {%0,%1,%2,%3};"
        : "+f"(c[0]), "+f"(c[1]), "+f"(c[2]), "+f"(c[3])
        : "r"(a[0]), "r"(a[1]), "r"(a[2]), "r"(a[3]), "r"(b[0]), "r"(b[1]));
}
#define SW64(o) ((o) ^ (((o) >> 3) & 0x30))

// one WKV recurrence step (state update only)
__device__ __forceinline__ void wkv_step(float kt, float vt, float w,
                                         float& p, float& q, float& o) {
    float wo = w + o;
    float d  = wo - kt;
    float e  = __expf(-fabsf(d));
    bool ge  = (d >= 0.f);
    float A  = ge ? 1.f : e;
    float Bv = ge ? e : 1.f;
    p = fmaf(A, p, Bv * vt);
    q = fmaf(A, q, Bv);
    o = fmaxf(wo, kt);
}
// output + state update
__device__ __forceinline__ float wkv_out_step(float kt, float vt, float w, float u,
                                              float& p, float& q, float& o) {
    float uk = u + kt;
    float d1 = o - uk;
    float e1 = __expf(-fabsf(d1));
    bool g1  = (d1 >= 0.f);
    float A1 = g1 ? 1.f : e1;
    float B1 = g1 ? e1 : 1.f;
    float y  = fmaf(A1, p, B1 * vt) / fmaf(A1, q, B1);
    wkv_step(kt, vt, w, p, q, o);
    return y;
}

// ---------------- kernel 1: q_shift + zigzag -> fp16 ----------------
__global__ void shift_zigzag_f16(const float* __restrict__ x, __half* __restrict__ a) {
    int gid = blockIdx.x * 256 + threadIdx.x;       // float4 units
    int c4 = gid & 127;
    int tp = (gid >> 7) & (TT - 1);
    int b  = gid >> 19;
    int i  = tp >> 6;
    int jj = tp & 63;
    int col = (i & 1) ? (63 - jj) : jj;
    int grp = c4 >> 5;
    int hs = i, ws = col;
    bool valid;
    if (grp == 0)      { ws = col - 1; valid = (col >= 1);  }
    else if (grp == 1) { ws = col + 1; valid = (col <= 62); }
    else if (grp == 2) { hs = i - 1;   valid = (i >= 1);    }
    else               { hs = i + 1;   valid = (i <= 62);   }
    float4 v = make_float4(0.f, 0.f, 0.f, 0.f);
    if (valid)
        v = *(const float4*)(x + ((size_t)((b << 12) + (hs << 6) + ws) << 9) + (c4 << 2));
    __half h[4] = {__float2half_rn(v.x), __float2half_rn(v.y),
                   __float2half_rn(v.z), __float2half_rn(v.w)};
    *(uint2*)(a + ((size_t)gid << 2)) = *(uint2*)h;
}

// ---------------- kernel 2: weight fp16 conversion ----------------
__global__ void conv_w4(const float* __restrict__ w0, const float* __restrict__ w1,
                        const float* __restrict__ w2, const float* __restrict__ w3,
                        __half* __restrict__ wo) {
    int gid = blockIdx.x * 256 + threadIdx.x;
    int sel = gid >> 18;
    int off = gid & (CC * CC - 1);
    const float* src = (sel == 0) ? w0 : (sel == 1) ? w1 : (sel == 2) ? w2 : w3;
    wo[gid] = __float2half_rn(src[off]);
}

// ---------------- GEMM: fp16 1-mma, 128x128 tiles, 3-stage pipe ------
#define TILE_B (128 * 64)
#define STG_B  (2 * TILE_B)        // 16 KB
#define SM_TOT (3 * STG_B)         // 48 KB

__device__ __forceinline__ void gemm_core(const __half* __restrict__ A,
                                          const __half* __restrict__ W,
                                          float* __restrict__ Co,
                                          __half* __restrict__ HCo,
                                          int m0, int n0, bool sigm, bool half_out,
                                          char* smem) {
    const int tid = threadIdx.x;
    const int wid = tid >> 5;
    const int lane = tid & 31;
    const int wm = (wid & 3) * 32;
    const int wn = (wid >> 2) * 64;
    const uint32_t sb0 = smem_u32(smem);

    float acc[2][8][4];
    #pragma unroll
    for (int i = 0; i < 2; i++)
        #pragma unroll
        for (int j = 0; j < 8; j++)
            #pragma unroll
            for (int q = 0; q < 4; q++) acc[i][j][q] = 0.f;

    auto load_stage = [&](int kc, int s) {
        uint32_t sb = sb0 + s * STG_B;
        #pragma unroll
        for (int i = 0; i < 2; i++) {
            int idx = tid + i * 256;
            int r = idx >> 2, c16 = idx & 3;
            uint32_t sw = SW64((uint32_t)(r * 64 + c16 * 16));
            size_t ga = (size_t)(m0 + r) * GK + kc * 32 + c16 * 8;
            size_t gb = (size_t)(n0 + r) * GK + kc * 32 + c16 * 8;
            cp16(sb + sw,          A + ga);
            cp16(sb + TILE_B + sw, W + gb);
        }
    };

    const int sub = lane >> 3, lrow = lane & 7;

    load_stage(0, 0); CP_COMMIT();
    load_stage(1, 1); CP_COMMIT();

    #pragma unroll 1
    for (int kc = 0; kc < 16; kc++) {
        if (kc < 14) { CP_WAIT1(); } else { CP_WAIT0(); }
        __syncthreads();
        if (kc + 2 < 16) {
            int s2 = (kc + 2) % 3;
            load_stage(kc + 2, s2); CP_COMMIT();
        }
        const uint32_t sb = sb0 + (kc % 3) * STG_B;

        #pragma unroll
        for (int k16 = 0; k16 < 2; k16++) {
            const uint32_t kbyte = (uint32_t)(k16 * 32 + (sub >> 1) * 16);
            uint32_t av[2][4], bh[8][2];
            #pragma unroll
            for (int mt = 0; mt < 2; mt++) {
                int row = wm + mt * 16 + (sub & 1) * 8 + lrow;
                uint32_t so = SW64((uint32_t)(row * 64) + kbyte);
                ldsm4(av[mt], sb + so);
            }
            #pragma unroll
            for (int nt = 0; nt < 4; nt++) {
                int row = wn + nt * 16 + (sub & 1) * 8 + lrow;
                uint32_t so = SW64((uint32_t)(row * 64) + kbyte);
                uint32_t t0[4];
                ldsm4(t0, sb + TILE_B + so);
                bh[2*nt][0] = t0[0]; bh[2*nt+1][0] = t0[1];
                bh[2*nt][1] = t0[2]; bh[2*nt+1][1] = t0[3];
            }
            #pragma unroll
            for (int mt = 0; mt < 2; mt++)
                #pragma unroll
                for (int n8 = 0; n8 < 8; n8++)
                    mma16816(acc[mt][n8], av[mt], bh[n8]);
        }
    }

    const int g = lane >> 2, t = lane & 3;
    #pragma unroll
    for (int mt = 0; mt < 2; mt++) {
        #pragma unroll
        for (int n8 = 0; n8 < 8; n8++) {
            int row0 = m0 + wm + mt * 16 + g;
            int col  = n0 + wn + n8 * 8 + t * 2;
            float c0 = acc[mt][n8][0], c1 = acc[mt][n8][1];
            float c2 = acc[mt][n8][2], c3 = acc[mt][n8][3];
            if (sigm) {
                c0 = 1.f / (1.f + __expf(-c0));
                c1 = 1.f / (1.f + __expf(-c1));
                c2 = 1.f / (1.f + __expf(-c2));
                c3 = 1.f / (1.f + __expf(-c3));
            }
            if (half_out) {
                *(__half2*)(HCo + (size_t)row0 * CC + col)       = __floats2half2_rn(c0, c1);
                *(__half2*)(HCo + (size_t)(row0 + 8) * CC + col) = __floats2half2_rn(c2, c3);
            } else {
                *(float2*)(Co + (size_t)row0 * CC + col)       = make_float2(c0, c1);
                *(float2*)(Co + (size_t)(row0 + 8) * CC + col) = make_float2(c2, c3);
            }
        }
    }
}

// fused k|v|sr: all three emitted fp16
__global__ __launch_bounds__(256) void gemm3_f16(const __half* __restrict__ A,
                                                 const __half* __restrict__ W,
                                                 __half* __restrict__ Kh,
                                                 __half* __restrict__ Vh,
                                                 __half* __restrict__ Sh) {
    extern __shared__ char smem[];
    const int which = blockIdx.x >> 2;
    const int n0 = (blockIdx.x & 3) * 128;
    const int m0 = blockIdx.y * 128;
    __half* HCo = (which == 0) ? Kh : (which == 1) ? Vh : Sh;
    gemm_core(A, W + (size_t)which * CC * CC, nullptr, HCo, m0, n0,
              which == 2, true, smem);
}

__global__ __launch_bounds__(256) void gemm1_f16(const __half* __restrict__ A,
                                                 const __half* __restrict__ W,
                                                 float* __restrict__ Co) {
    extern __shared__ char smem[];
    gemm_core(A, W, Co, nullptr, blockIdx.y * 128, blockIdx.x * 128, false, false, smem);
}

// ---------------- WKV scans: 4 ch/thread, 256 chunks of 16, 1024 thr ----------
#define NCHUNK 256
#define CHL    (TT / NCHUNK)   // 16
#define LPB    4               // lanes per chunk-row (each lane = 4 channels)
#define CHB    (LPB * 4)       // 16 channels per block
#define WKV_SMEM (3 * NCHUNK * CHB * 4)   // 49152 bytes

__global__ __launch_bounds__(1024) void wkv1(const float* __restrict__ decay,
                                             const float* __restrict__ first,
                                             const __half* __restrict__ K,
                                             const __half* __restrict__ V,
                                             __half* __restrict__ Y) {
    extern __shared__ float dsm[];
    float* sp = dsm;                       // [NCHUNK][CHB]
    float* sq = dsm + NCHUNK * CHB;
    float* so = dsm + 2 * NCHUNK * CHB;
    const int tid = threadIdx.x;
    const int cl = tid & (LPB - 1);
    const int ch = tid >> 2;               // chunk 0..255
    const int cg = blockIdx.x & 31;        // 32 channel groups
    const int b  = blockIdx.x >> 5;
    const int c0 = cg * CHB + cl * 4;
    const float inv_t = 1.0f / (float)TT;
    float w[4], u[4];
    #pragma unroll
    for (int j = 0; j < 4; j++) {
        w[j] = decay[c0 + j] * inv_t;
        u[j] = first[c0 + j] * inv_t;
    }
    const size_t base = ((size_t)(b * TT + ch * CHL)) * CC + c0;

    float p[4], q[4], o[4];
    #pragma unroll
    for (int j = 0; j < 4; j++) { p[j] = 0.f; q[j] = 0.f; o[j] = -1e38f; }

    #pragma unroll 4
    for (int s = 0; s < CHL; s++) {
        uint2 kr = *(const uint2*)(K + base + (size_t)s * CC);
        uint2 vr = *(const uint2*)(V + base + (size_t)s * CC);
        float2 k01 = __half22float2(*(__half2*)&kr.x);
        float2 k23 = __half22float2(*(__half2*)&kr.y);
        float2 v01 = __half22float2(*(__half2*)&vr.x);
        float2 v23 = __half22float2(*(__half2*)&vr.y);
        wkv_step(k01.x, v01.x, w[0], p[0], q[0], o[0]);
        wkv_step(k01.y, v01.y, w[1], p[1], q[1], o[1]);
        wkv_step(k23.x, v23.x, w[2], p[2], q[2], o[2]);
        wkv_step(k23.y, v23.y, w[3], p[3], q[3], o[3]);
    }
    #pragma unroll
    for (int j = 0; j < 4; j++) {
        sp[ch * CHB + cl * 4 + j] = p[j];
        sq[ch * CHB + cl * 4 + j] = q[j];
        so[ch * CHB + cl * 4 + j] = o[j];
    }
    __syncthreads();

    // exclusive prefix over chunks: 16 threads, one channel each
    if (tid < CHB) {
        const float Lw = (float)CHL * decay[cg * CHB + tid] * inv_t;
        float ap = 0.f, aq = 0.f, ao = -1e38f;
        #pragma unroll 8
        for (int i = 0; i < NCHUNK; i++) {
            int ix = i * CHB + tid;
            float tp = sp[ix], tq = sq[ix], to = so[ix];
            sp[ix] = ap; sq[ix] = aq; so[ix] = ao;
            float od = ao + Lw;
            float d  = od - to;
            float e  = __expf(-fabsf(d));
            bool ge  = (d >= 0.f);
            float e1 = ge ? 1.f : e;
            float e2 = ge ? e : 1.f;
            ap = fmaf(e1, ap, e2 * tp);
            aq = fmaf(e1, aq, e2 * tq);
            ao = fmaxf(od, to);
        }
    }
    __syncthreads();
    #pragma unroll
    for (int j = 0; j < 4; j++) {
        p[j] = sp[ch * CHB + cl * 4 + j];
        q[j] = sq[ch * CHB + cl * 4 + j];
        o[j] = so[ch * CHB + cl * 4 + j];
    }

    #pragma unroll 4
    for (int s = 0; s < CHL; s++) {
        size_t idx = base + (size_t)s * CC;
        uint2 kr = *(const uint2*)(K + idx);
        uint2 vr = *(const uint2*)(V + idx);
        float2 k01 = __half22float2(*(__half2*)&kr.x);
        float2 k23 = __half22float2(*(__half2*)&kr.y);
        float2 v01 = __half22float2(*(__half2*)&vr.x);
        float2 v23 = __half22float2(*(__half2*)&vr.y);
        float y0 = wkv_out_step(k01.x, v01.x, w[0], u[0], p[0], q[0], o[0]);
        float y1 = wkv_out_step(k01.y, v01.y, w[1], u[1], p[1], q[1], o[1]);
        float y2 = wkv_out_step(k23.x, v23.x, w[2], u[2], p[2], q[2], o[2]);
        float y3 = wkv_out_step(k23.y, v23.y, w[3], u[3], p[3], q[3], o[3]);
        uint2 yr;
        *(__half2*)&yr.x = __floats2half2_rn(y0, y1);
        *(__half2*)&yr.y = __floats2half2_rn(y2, y3);
        *(uint2*)(Y + idx) = yr;
    }
}

// scan 2: zigzag-gathered reads (fused permute); epilogue writes fp16 sr*y.
__global__ __launch_bounds__(1024) void wkv2(const float* __restrict__ decay,
                                             const float* __restrict__ first,
                                             const __half* __restrict__ K,
                                             const __half* __restrict__ V,
                                             const __half* __restrict__ SR,
                                             __half* __restrict__ Ao) {
    extern __shared__ float dsm[];
    float* sp = dsm;
    float* sq = dsm + NCHUNK * CHB;
    float* so = dsm + 2 * NCHUNK * CHB;
    const int tid = threadIdx.x;
    const int cl = tid & (LPB - 1);
    const int ch = tid >> 2;               // chunk 0..255 (quarter image row)
    const int cg = blockIdx.x & 31;
    const int b  = blockIdx.x >> 5;
    const int c0 = cg * CHB + cl * 4;
    const float inv_t = 1.0f / (float)TT;
    float w[4], u[4];
    #pragma unroll
    for (int j = 0; j < 4; j++) {
        w[j] = decay[CC + c0 + j] * inv_t;
        u[j] = first[CC + c0 + j] * inv_t;
    }
    const int irow = ch >> 2;              // image row
    const int jbase = (ch & 3) << 4;       // 0,16,32,48 within the row's zigzag order
    const bool rev = (irow & 1);
    const size_t brow = ((size_t)(b << 12) + (irow << 6));

    float p[4], q[4], o[4];
    #pragma unroll
    for (int j = 0; j < 4; j++) { p[j] = 0.f; q[j] = 0.f; o[j] = -1e38f; }

    #pragma unroll 4
    for (int s = 0; s < CHL; s++) {
        int jj = jbase + s;
        int col = rev ? (63 - jj) : jj;
        size_t idx = (brow + col) * CC + c0;
        uint2 kr = *(const uint2*)(K + idx);
        uint2 vr = *(const uint2*)(V + idx);
        float2 k01 = __half22float2(*(__half2*)&kr.x);
        float2 k23 = __half22float2(*(__half2*)&kr.y);
        float2 v01 = __half22float2(*(__half2*)&vr.x);
        float2 v23 = __half22float2(*(__half2*)&vr.y);
        wkv_step(k01.x, v01.x, w[0], p[0], q[0], o[0]);
        wkv_step(k01.y, v01.y, w[1], p[1], q[1], o[1]);
        wkv_step(k23.x, v23.x, w[2], p[2], q[2], o[2]);
        wkv_step(k23.y, v23.y, w[3], p[3], q[3], o[3]);
    }
    #pragma unroll
    for (int j = 0; j < 4; j++) {
        sp[ch * CHB + cl * 4 + j] = p[j];
        sq[ch * CHB + cl * 4 + j] = q[j];
        so[ch * CHB + cl * 4 + j] = o[j];
    }
    __syncthreads();

    if (tid < CHB) {
        const float Lw = (float)CHL * decay[CC + cg * CHB + tid] * inv_t;
        float ap = 0.f, aq = 0.f, ao = -1e38f;
        #pragma unroll 8
        for (int i = 0; i < NCHUNK; i++) {
            int ix = i * CHB + tid;
            float tp = sp[ix], tq = sq[ix], to = so[ix];
            sp[ix] = ap; sq[ix] = aq; so[ix] = ao;
            float od = ao + Lw;
            float d  = od - to;
            float e  = __expf(-fabsf(d));
            bool ge  = (d >= 0.f);
            float e1 = ge ? 1.f : e;
            float e2 = ge ? e : 1.f;
            ap = fmaf(e1, ap, e2 * tp);
            aq = fmaf(e1, aq, e2 * tq);
            ao = fmaxf(od, to);
        }
    }
    __syncthreads();
    #pragma unroll
    for (int j = 0; j < 4; j++) {
        p[j] = sp[ch * CHB + cl * 4 + j];
        q[j] = sq[ch * CHB + cl * 4 + j];
        o[j] = so[ch * CHB + cl * 4 + j];
    }

    #pragma unroll 4
    for (int s = 0; s < CHL; s++) {
        int jj = jbase + s;
        int col = rev ? (63 - jj) : jj;
        size_t idx = (brow + col) * CC + c0;
        size_t odx = ((size_t)(b * TT + ch * CHL + s)) * CC + c0;
        uint2 kr = *(const uint2*)(K + idx);
        uint2 vr = *(const uint2*)(V + idx);
        float2 k01 = __half22float2(*(__half2*)&kr.x);
        float2 k23 = __half22float2(*(__half2*)&kr.y);
        float2 v01 = __half22float2(*(__half2*)&vr.x);
        float2 v23 = __half22float2(*(__half2*)&vr.y);
        float y0 = wkv_out_step(k01.x, v01.x, w[0], u[0], p[0], q[0], o[0]);
        float y1 = wkv_out_step(k01.y, v01.y, w[1], u[1], p[1], q[1], o[1]);
        float y2 = wkv_out_step(k23.x, v23.x, w[2], u[2], p[2], q[2], o[2]);
        float y3 = wkv_out_step(k23.y, v23.y, w[3], u[3], p[3], q[3], o[3]);
        uint2 sr = *(const uint2*)(SR + odx);
        float2 s01 = __half22float2(*(__half2*)&sr.x);
        float2 s23 = __half22float2(*(__half2*)&sr.y);
        uint2 ar;
        *(__half2*)&ar.x = __floats2half2_rn(s01.x * y0, s01.y * y1);
        *(__half2*)&ar.y = __floats2half2_rn(s23.x * y2, s23.y * y3);
        *(uint2*)(Ao + odx) = ar;
    }
}

// ---------------- launch ----------------
extern "C" void kernel_launch(void* const* d_in, const int* in_sizes, int n_in,
                              void* d_out, int out_size) {
    const float* x       = (const float*)d_in[0];
    const float* W_key   = (const float*)d_in[1];
    const float* W_value = (const float*)d_in[2];
    const float* W_recep = (const float*)d_in[3];
    const float* W_out   = (const float*)d_in[4];
    const float* decay   = (const float*)d_in[5];
    const float* first   = (const float*)d_in[6];
    float* out = (float*)d_out;

    __half *kh, *vh, *srh, *a, *w;
    cudaGetSymbolAddress((void**)&kh,  g_kh);
    cudaGetSymbolAddress((void**)&vh,  g_vh);
    cudaGetSymbolAddress((void**)&srh, g_srh);
    cudaGetSymbolAddress((void**)&a,   g_a);
    cudaGetSymbolAddress((void**)&w,   g_w);

    cudaFuncSetAttribute(gemm3_f16, cudaFuncAttributeMaxDynamicSharedMemorySize, SM_TOT);
    cudaFuncSetAttribute(gemm1_f16, cudaFuncAttributeMaxDynamicSharedMemorySize, SM_TOT);

    dim3 eb(256), eg(BTC / 4 / 256);
    dim3 cg(4 * CC * CC / 256);
    dim3 gb(256), gg3(12, GM / 128), gg1(4, GM / 128);
    dim3 wb(1024), wg(BB * (CC / CHB));    // 256 blocks

    shift_zigzag_f16<<<eg, eb>>>(x, a);
    conv_w4<<<cg, eb>>>(W_key, W_value, W_recep, W_out, w);
    gemm3_f16<<<gg3, gb, SM_TOT>>>(a, w, kh, vh, srh);
    wkv1<<<wg, wb, WKV_SMEM>>>(decay, first, kh, vh, vh);
    wkv2<<<wg, wb, WKV_SMEM>>>(decay, first, kh, vh, srh, a);
    gemm1_f16<<<gg1, gb, SM_TOT>>>(a, w + 3 * (size_t)CC * CC, out);
}

// round 17
// speedup vs baseline: 1.1169x; 1.0166x over previous
#include <cuda_runtime.h>
#include <cuda_fp16.h>
#include <math.h>
#include <stdint.h>

// Fixed problem shape: B=8, H=W=64 -> T=4096, C=512
#define BB   8
#define TT   4096
#define CC   512
#define BTC  (BB*TT*CC)
#define GM   32768
#define GK   512

// ---------------- scratch ----------------
__device__ __half g_kh[BTC];          // k (fp16)
__device__ __half g_vh[BTC];          // v -> y1 in place (fp16)
__device__ __half g_srh[BTC];         // sr (fp16)
__device__ __half g_a [BTC];          // GEMM A (xi, then sr*y2), fp16
__device__ __half g_w [4*CC*CC];      // weights, fp16

// ---------------- asm helpers ----------------
__device__ __forceinline__ uint32_t smem_u32(const void* p) {
    uint32_t a;
    asm("{ .reg .u64 t; cvta.to.shared.u64 t, %1; cvt.u32.u64 %0, t; }" : "=r"(a) : "l"(p));
    return a;
}
__device__ __forceinline__ void cp16(uint32_t d, const void* s) {
    asm volatile("cp.async.cg.shared.global [%0], [%1], 16;" :: "r"(d), "l"(s));
}
#define CP_COMMIT() asm volatile("cp.async.commit_group;" ::: "memory")
#define CP_WAIT0()  asm volatile("cp.async.wait_group 0;" ::: "memory")
#define CP_WAIT1()  asm volatile("cp.async.wait_group 1;" ::: "memory")

__device__ __forceinline__ void ldsm4(uint32_t* r, uint32_t a) {
    asm volatile("ldmatrix.sync.aligned.m8n8.x4.shared.b16 {%0,%1,%2,%3}, [%4];"
        : "=r"(r[0]), "=r"(r[1]), "=r"(r[2]), "=r"(r[3]) : "r"(a));
}
__device__ __forceinline__ void mma16816(float* c, const uint32_t* a, const uint32_t* b) {
    asm volatile("mma.sync.aligned.m16n8k16.row.col.f32.f16.f16.f32 "
        "{%0,%1,%2,%3}, {%4,%5,%6,%7}, {%8,%9}, {%0,%1,%2,%3};"
        : "+f"(c[0]), "+f"(c[1]), "+f"(c[2]), "+f"(c[3])
        : "r"(a[0]), "r"(a[1]), "r"(a[2]), "r"(a[3]), "r"(b[0]), "r"(b[1]));
}
#define SW64(o) ((o) ^ (((o) >> 3) & 0x30))

// one WKV recurrence step (state update only)
__device__ __forceinline__ void wkv_step(float kt, float vt, float w,
                                         float& p, float& q, float& o) {
    float wo = w + o;
    float d  = wo - kt;
    float e  = __expf(-fabsf(d));
    bool ge  = (d >= 0.f);
    float A  = ge ? 1.f : e;
    float Bv = ge ? e : 1.f;
    p = fmaf(A, p, Bv * vt);
    q = fmaf(A, q, Bv);
    o = fmaxf(wo, kt);
}
// output + state update
__device__ __forceinline__ float wkv_out_step(float kt, float vt, float w, float u,
                                              float& p, float& q, float& o) {
    float uk = u + kt;
    float d1 = o - uk;
    float e1 = __expf(-fabsf(d1));
    bool g1  = (d1 >= 0.f);
    float A1 = g1 ? 1.f : e1;
    float B1 = g1 ? e1 : 1.f;
    float y  = fmaf(A1, p, B1 * vt) / fmaf(A1, q, B1);
    wkv_step(kt, vt, w, p, q, o);
    return y;
}

// ---------------- kernel 1: q_shift + zigzag -> fp16 ----------------
__global__ void shift_zigzag_f16(const float* __restrict__ x, __half* __restrict__ a) {
    int gid = blockIdx.x * 256 + threadIdx.x;       // float4 units
    int c4 = gid & 127;
    int tp = (gid >> 7) & (TT - 1);
    int b  = gid >> 19;
    int i  = tp >> 6;
    int jj = tp & 63;
    int col = (i & 1) ? (63 - jj) : jj;
    int grp = c4 >> 5;
    int hs = i, ws = col;
    bool valid;
    if (grp == 0)      { ws = col - 1; valid = (col >= 1);  }
    else if (grp == 1) { ws = col + 1; valid = (col <= 62); }
    else if (grp == 2) { hs = i - 1;   valid = (i >= 1);    }
    else               { hs = i + 1;   valid = (i <= 62);   }
    float4 v = make_float4(0.f, 0.f, 0.f, 0.f);
    if (valid)
        v = *(const float4*)(x + ((size_t)((b << 12) + (hs << 6) + ws) << 9) + (c4 << 2));
    __half h[4] = {__float2half_rn(v.x), __float2half_rn(v.y),
                   __float2half_rn(v.z), __float2half_rn(v.w)};
    *(uint2*)(a + ((size_t)gid << 2)) = *(uint2*)h;
}

// ---------------- kernel 2: weight fp16 conversion ----------------
__global__ void conv_w4(const float* __restrict__ w0, const float* __restrict__ w1,
                        const float* __restrict__ w2, const float* __restrict__ w3,
                        __half* __restrict__ wo) {
    int gid = blockIdx.x * 256 + threadIdx.x;
    int sel = gid >> 18;
    int off = gid & (CC * CC - 1);
    const float* src = (sel == 0) ? w0 : (sel == 1) ? w1 : (sel == 2) ? w2 : w3;
    wo[gid] = __float2half_rn(src[off]);
}

// ---------------- GEMM: fp16 1-mma, 128x128 tiles, 3-stage pipe ------
#define TILE_B (128 * 64)
#define STG_B  (2 * TILE_B)        // 16 KB
#define SM_TOT (3 * STG_B)         // 48 KB

__device__ __forceinline__ void gemm_core(const __half* __restrict__ A,
                                          const __half* __restrict__ W,
                                          float* __restrict__ Co,
                                          __half* __restrict__ HCo,
                                          int m0, int n0, bool sigm, bool half_out,
                                          char* smem) {
    const int tid = threadIdx.x;
    const int wid = tid >> 5;
    const int lane = tid & 31;
    const int wm = (wid & 3) * 32;
    const int wn = (wid >> 2) * 64;
    const uint32_t sb0 = smem_u32(smem);

    float acc[2][8][4];
    #pragma unroll
    for (int i = 0; i < 2; i++)
        #pragma unroll
        for (int j = 0; j < 8; j++)
            #pragma unroll
            for (int q = 0; q < 4; q++) acc[i][j][q] = 0.f;

    auto load_stage = [&](int kc, int s) {
        uint32_t sb = sb0 + s * STG_B;
        #pragma unroll
        for (int i = 0; i < 2; i++) {
            int idx = tid + i * 256;
            int r = idx >> 2, c16 = idx & 3;
            uint32_t sw = SW64((uint32_t)(r * 64 + c16 * 16));
            size_t ga = (size_t)(m0 + r) * GK + kc * 32 + c16 * 8;
            size_t gb = (size_t)(n0 + r) * GK + kc * 32 + c16 * 8;
            cp16(sb + sw,          A + ga);
            cp16(sb + TILE_B + sw, W + gb);
        }
    };

    const int sub = lane >> 3, lrow = lane & 7;

    load_stage(0, 0); CP_COMMIT();
    load_stage(1, 1); CP_COMMIT();

    #pragma unroll 1
    for (int kc = 0; kc < 16; kc++) {
        if (kc < 14) { CP_WAIT1(); } else { CP_WAIT0(); }
        __syncthreads();
        if (kc + 2 < 16) {
            int s2 = (kc + 2) % 3;
            load_stage(kc + 2, s2); CP_COMMIT();
        }
        const uint32_t sb = sb0 + (kc % 3) * STG_B;

        #pragma unroll
        for (int k16 = 0; k16 < 2; k16++) {
            const uint32_t kbyte = (uint32_t)(k16 * 32 + (sub >> 1) * 16);
            uint32_t av[2][4], bh[8][2];
            #pragma unroll
            for (int mt = 0; mt < 2; mt++) {
                int row = wm + mt * 16 + (sub & 1) * 8 + lrow;
                uint32_t so = SW64((uint32_t)(row * 64) + kbyte);
                ldsm4(av[mt], sb + so);
            }
            #pragma unroll
            for (int nt = 0; nt < 4; nt++) {
                int row = wn + nt * 16 + (sub & 1) * 8 + lrow;
                uint32_t so = SW64((uint32_t)(row * 64) + kbyte);
                uint32_t t0[4];
                ldsm4(t0, sb + TILE_B + so);
                bh[2*nt][0] = t0[0]; bh[2*nt+1][0] = t0[1];
                bh[2*nt][1] = t0[2]; bh[2*nt+1][1] = t0[3];
            }
            #pragma unroll
            for (int mt = 0; mt < 2; mt++)
                #pragma unroll
                for (int n8 = 0; n8 < 8; n8++)
                    mma16816(acc[mt][n8], av[mt], bh[n8]);
        }
    }

    const int g = lane >> 2, t = lane & 3;
    #pragma unroll
    for (int mt = 0; mt < 2; mt++) {
        #pragma unroll
        for (int n8 = 0; n8 < 8; n8++) {
            int row0 = m0 + wm + mt * 16 + g;
            int col  = n0 + wn + n8 * 8 + t * 2;
            float c0 = acc[mt][n8][0], c1 = acc[mt][n8][1];
            float c2 = acc[mt][n8][2], c3 = acc[mt][n8][3];
            if (sigm) {
                c0 = 1.f / (1.f + __expf(-c0));
                c1 = 1.f / (1.f + __expf(-c1));
                c2 = 1.f / (1.f + __expf(-c2));
                c3 = 1.f / (1.f + __expf(-c3));
            }
            if (half_out) {
                *(__half2*)(HCo + (size_t)row0 * CC + col)       = __floats2half2_rn(c0, c1);
                *(__half2*)(HCo + (size_t)(row0 + 8) * CC + col) = __floats2half2_rn(c2, c3);
            } else {
                *(float2*)(Co + (size_t)row0 * CC + col)       = make_float2(c0, c1);
                *(float2*)(Co + (size_t)(row0 + 8) * CC + col) = make_float2(c2, c3);
            }
        }
    }
}

// fused k|v|sr: all three emitted fp16
__global__ __launch_bounds__(256) void gemm3_f16(const __half* __restrict__ A,
                                                 const __half* __restrict__ W,
                                                 __half* __restrict__ Kh,
                                                 __half* __restrict__ Vh,
                                                 __half* __restrict__ Sh) {
    extern __shared__ char smem[];
    const int which = blockIdx.x >> 2;
    const int n0 = (blockIdx.x & 3) * 128;
    const int m0 = blockIdx.y * 128;
    __half* HCo = (which == 0) ? Kh : (which == 1) ? Vh : Sh;
    gemm_core(A, W + (size_t)which * CC * CC, nullptr, HCo, m0, n0,
              which == 2, true, smem);
}

__global__ __launch_bounds__(256) void gemm1_f16(const __half* __restrict__ A,
                                                 const __half* __restrict__ W,
                                                 float* __restrict__ Co) {
    extern __shared__ char smem[];
    gemm_core(A, W, Co, nullptr, blockIdx.y * 128, blockIdx.x * 128, false, false, smem);
}

// ---------------- wkv1: 2 ch/thread, 128 chunks of 32, 1024 thr (R14 best) ---
#define NCHUNK1 128
#define CHL1    (TT / NCHUNK1)   // 32
#define LPB1    8                // lanes per chunk-row (each lane = 2 channels)
#define CHB1    (LPB1 * 2)       // 16 channels per block

__global__ __launch_bounds__(1024) void wkv1(const float* __restrict__ decay,
                                             const float* __restrict__ first,
                                             const __half* __restrict__ K,
                                             const __half* __restrict__ V,
                                             __half* __restrict__ Y) {
    __shared__ float sp[NCHUNK1][CHB1 + 1];
    __shared__ float sq[NCHUNK1][CHB1 + 1];
    __shared__ float so[NCHUNK1][CHB1 + 1];
    const int tid = threadIdx.x;
    const int cl = tid & (LPB1 - 1);
    const int ch = tid / LPB1;             // chunk 0..127
    const int cg = blockIdx.x & 31;        // 32 channel groups
    const int b  = blockIdx.x >> 5;
    const int c0 = cg * CHB1 + cl * 2;
    const float inv_t = 1.0f / (float)TT;
    const float w0 = decay[c0] * inv_t,     w1 = decay[c0 + 1] * inv_t;
    const float u0 = first[c0] * inv_t,     u1 = first[c0 + 1] * inv_t;
    const size_t base = ((size_t)(b * TT + ch * CHL1)) * CC + c0;

    float p0 = 0.f, q0 = 0.f, o0 = -1e38f;
    float p1 = 0.f, q1 = 0.f, o1 = -1e38f;
    #pragma unroll 8
    for (int s = 0; s < CHL1; s++) {
        float2 kk = __half22float2(*(const __half2*)(K + base + (size_t)s * CC));
        float2 vv = __half22float2(*(const __half2*)(V + base + (size_t)s * CC));
        wkv_step(kk.x, vv.x, w0, p0, q0, o0);
        wkv_step(kk.y, vv.y, w1, p1, q1, o1);
    }
    sp[ch][cl*2] = p0; sq[ch][cl*2] = q0; so[ch][cl*2] = o0;
    sp[ch][cl*2+1] = p1; sq[ch][cl*2+1] = q1; so[ch][cl*2+1] = o1;
    __syncthreads();

    // exclusive prefix over chunks: 16 threads (ch<2), one channel each
    if (ch < 2) {
        int cc = cl * 2 + ch;
        const float Lw = (float)CHL1 * ((ch == 0) ? w0 : w1);
        float ap = 0.f, aq = 0.f, ao = -1e38f;
        #pragma unroll 8
        for (int i = 0; i < NCHUNK1; i++) {
            float tp = sp[i][cc], tq = sq[i][cc], to = so[i][cc];
            sp[i][cc] = ap; sq[i][cc] = aq; so[i][cc] = ao;
            float od = ao + Lw;
            float d  = od - to;
            float e  = __expf(-fabsf(d));
            bool ge  = (d >= 0.f);
            float e1 = ge ? 1.f : e;
            float e2 = ge ? e : 1.f;
            ap = fmaf(e1, ap, e2 * tp);
            aq = fmaf(e1, aq, e2 * tq);
            ao = fmaxf(od, to);
        }
    }
    __syncthreads();
    p0 = sp[ch][cl*2]; q0 = sq[ch][cl*2]; o0 = so[ch][cl*2];
    p1 = sp[ch][cl*2+1]; q1 = sq[ch][cl*2+1]; o1 = so[ch][cl*2+1];

    #pragma unroll 8
    for (int s = 0; s < CHL1; s++) {
        size_t idx = base + (size_t)s * CC;
        float2 kk = __half22float2(*(const __half2*)(K + idx));
        float2 vv = __half22float2(*(const __half2*)(V + idx));
        float y0 = wkv_out_step(kk.x, vv.x, w0, u0, p0, q0, o0);
        float y1 = wkv_out_step(kk.y, vv.y, w1, u1, p1, q1, o1);
        *(__half2*)(Y + idx) = __floats2half2_rn(y0, y1);
    }
}

// ---------------- wkv2: 4 ch/thread, 256 chunks of 16, 1024 thr (R15) --------
#define NCHUNK2 256
#define CHL2    (TT / NCHUNK2)   // 16
#define LPB2    4                // lanes per chunk-row (each lane = 4 channels)
#define CHB2    (LPB2 * 4)       // 16 channels per block
#define WKV2_SMEM (3 * NCHUNK2 * CHB2 * 4)   // 49152 bytes

__global__ __launch_bounds__(1024) void wkv2(const float* __restrict__ decay,
                                             const float* __restrict__ first,
                                             const __half* __restrict__ K,
                                             const __half* __restrict__ V,
                                             const __half* __restrict__ SR,
                                             __half* __restrict__ Ao) {
    extern __shared__ float dsm[];
    float* sp = dsm;
    float* sq = dsm + NCHUNK2 * CHB2;
    float* so = dsm + 2 * NCHUNK2 * CHB2;
    const int tid = threadIdx.x;
    const int cl = tid & (LPB2 - 1);
    const int ch = tid >> 2;               // chunk 0..255 (quarter image row)
    const int cg = blockIdx.x & 31;
    const int b  = blockIdx.x >> 5;
    const int c0 = cg * CHB2 + cl * 4;
    const float inv_t = 1.0f / (float)TT;
    float w[4], u[4];
    #pragma unroll
    for (int j = 0; j < 4; j++) {
        w[j] = decay[CC + c0 + j] * inv_t;
        u[j] = first[CC + c0 + j] * inv_t;
    }
    const int irow = ch >> 2;              // image row
    const int jbase = (ch & 3) << 4;       // 0,16,32,48 within the row's zigzag order
    const bool rev = (irow & 1);
    const size_t brow = ((size_t)(b << 12) + (irow << 6));

    float p[4], q[4], o[4];
    #pragma unroll
    for (int j = 0; j < 4; j++) { p[j] = 0.f; q[j] = 0.f; o[j] = -1e38f; }

    #pragma unroll 4
    for (int s = 0; s < CHL2; s++) {
        int jj = jbase + s;
        int col = rev ? (63 - jj) : jj;
        size_t idx = (brow + col) * CC + c0;
        uint2 kr = *(const uint2*)(K + idx);
        uint2 vr = *(const uint2*)(V + idx);
        float2 k01 = __half22float2(*(__half2*)&kr.x);
        float2 k23 = __half22float2(*(__half2*)&kr.y);
        float2 v01 = __half22float2(*(__half2*)&vr.x);
        float2 v23 = __half22float2(*(__half2*)&vr.y);
        wkv_step(k01.x, v01.x, w[0], p[0], q[0], o[0]);
        wkv_step(k01.y, v01.y, w[1], p[1], q[1], o[1]);
        wkv_step(k23.x, v23.x, w[2], p[2], q[2], o[2]);
        wkv_step(k23.y, v23.y, w[3], p[3], q[3], o[3]);
    }
    #pragma unroll
    for (int j = 0; j < 4; j++) {
        sp[ch * CHB2 + cl * 4 + j] = p[j];
        sq[ch * CHB2 + cl * 4 + j] = q[j];
        so[ch * CHB2 + cl * 4 + j] = o[j];
    }
    __syncthreads();

    if (tid < CHB2) {
        const float Lw = (float)CHL2 * decay[CC + cg * CHB2 + tid] * inv_t;
        float ap = 0.f, aq = 0.f, ao = -1e38f;
        #pragma unroll 8
        for (int i = 0; i < NCHUNK2; i++) {
            int ix = i * CHB2 + tid;
            float tp = sp[ix], tq = sq[ix], to = so[ix];
            sp[ix] = ap; sq[ix] = aq; so[ix] = ao;
            float od = ao + Lw;
            float d  = od - to;
            float e  = __expf(-fabsf(d));
            bool ge  = (d >= 0.f);
            float e1 = ge ? 1.f : e;
            float e2 = ge ? e : 1.f;
            ap = fmaf(e1, ap, e2 * tp);
            aq = fmaf(e1, aq, e2 * tq);
            ao = fmaxf(od, to);
        }
    }
    __syncthreads();
    #pragma unroll
    for (int j = 0; j < 4; j++) {
        p[j] = sp[ch * CHB2 + cl * 4 + j];
        q[j] = sq[ch * CHB2 + cl * 4 + j];
        o[j] = so[ch * CHB2 + cl * 4 + j];
    }

    #pragma unroll 4
    for (int s = 0; s < CHL2; s++) {
        int jj = jbase + s;
        int col = rev ? (63 - jj) : jj;
        size_t idx = (brow + col) * CC + c0;
        size_t odx = ((size_t)(b * TT + ch * CHL2 + s)) * CC + c0;
        uint2 kr = *(const uint2*)(K + idx);
        uint2 vr = *(const uint2*)(V + idx);
        float2 k01 = __half22float2(*(__half2*)&kr.x);
        float2 k23 = __half22float2(*(__half2*)&kr.y);
        float2 v01 = __half22float2(*(__half2*)&vr.x);
        float2 v23 = __half22float2(*(__half2*)&vr.y);
        float y0 = wkv_out_step(k01.x, v01.x, w[0], u[0], p[0], q[0], o[0]);
        float y1 = wkv_out_step(k01.y, v01.y, w[1], u[1], p[1], q[1], o[1]);
        float y2 = wkv_out_step(k23.x, v23.x, w[2], u[2], p[2], q[2], o[2]);
        float y3 = wkv_out_step(k23.y, v23.y, w[3], u[3], p[3], q[3], o[3]);
        uint2 sr = *(const uint2*)(SR + odx);
        float2 s01 = __half22float2(*(__half2*)&sr.x);
        float2 s23 = __half22float2(*(__half2*)&sr.y);
        uint2 ar;
        *(__half2*)&ar.x = __floats2half2_rn(s01.x * y0, s01.y * y1);
        *(__half2*)&ar.y = __floats2half2_rn(s23.x * y2, s23.y * y3);
        *(uint2*)(Ao + odx) = ar;
    }
}

// ---------------- launch ----------------
extern "C" void kernel_launch(void* const* d_in, const int* in_sizes, int n_in,
                              void* d_out, int out_size) {
    const float* x       = (const float*)d_in[0];
    const float* W_key   = (const float*)d_in[1];
    const float* W_value = (const float*)d_in[2];
    const float* W_recep = (const float*)d_in[3];
    const float* W_out   = (const float*)d_in[4];
    const float* decay   = (const float*)d_in[5];
    const float* first   = (const float*)d_in[6];
    float* out = (float*)d_out;

    __half *kh, *vh, *srh, *a, *w;
    cudaGetSymbolAddress((void**)&kh,  g_kh);
    cudaGetSymbolAddress((void**)&vh,  g_vh);
    cudaGetSymbolAddress((void**)&srh, g_srh);
    cudaGetSymbolAddress((void**)&a,   g_a);
    cudaGetSymbolAddress((void**)&w,   g_w);

    cudaFuncSetAttribute(gemm3_f16, cudaFuncAttributeMaxDynamicSharedMemorySize, SM_TOT);
    cudaFuncSetAttribute(gemm1_f16, cudaFuncAttributeMaxDynamicSharedMemorySize, SM_TOT);

    dim3 eb(256), eg(BTC / 4 / 256);
    dim3 cg(4 * CC * CC / 256);
    dim3 gb(256), gg3(12, GM / 128), gg1(4, GM / 128);
    dim3 wb(1024), wg(BB * 32);            // 256 blocks

    shift_zigzag_f16<<<eg, eb>>>(x, a);
    conv_w4<<<cg, eb>>>(W_key, W_value, W_recep, W_out, w);
    gemm3_f16<<<gg3, gb, SM_TOT>>>(a, w, kh, vh, srh);
    wkv1<<<wg, wb>>>(decay, first, kh, vh, vh);
    wkv2<<<wg, wb, WKV2_SMEM>>>(decay, first, kh, vh, srh, a);
    gemm1_f16<<<gg1, gb, SM_TOT>>>(a, w + 3 * (size_t)CC * CC, out);
}